// round 8
// baseline (speedup 1.0000x reference)
#include <cuda_runtime.h>
#include <cuda_bf16.h>
#include <math.h>
#include <stdint.h>

#define D 128
#define EPS 1e-5f
#define PADX 132
#define NODE_CAP 20096
#define E_MAX 640000

static const int SMEM_BYTES = (128 * PADX + 128 * 128) * 4;  // SIMT kernels
// TC kernel smem: 6 tiles (Ah, Al, W1h, W1l, W2h, W2l), 128 rows x 272 bytes
#define TILE_PITCH 272
#define TILE_BYTES_PAD (128 * TILE_PITCH)  // 34816
static const int TC_SMEM = 6 * TILE_BYTES_PAD;  // 208896

// ---------------- scratch ----------------
__device__ float g_t1[(size_t)E_MAX * D];
__device__ float g_u [(size_t)E_MAX * D];
__device__ float g_v [(size_t)NODE_CAP * D];
__device__ float g_w [(size_t)NODE_CAP * D];
__device__ float g_P1[(size_t)NODE_CAP * D];
__device__ float g_P2[(size_t)NODE_CAP * D];
__device__ float g_agg[(size_t)NODE_CAP * D];
__device__ float g_deg[NODE_CAP];
__device__ float g_stats[5 * 2 * 128];
__device__ float g_bnA[5 * 128];
__device__ float g_bnC[5 * 128];
// prepped weights: 6 matrices x (hi,lo), each [n][k] bf16 128x128 = 32KB
__device__ __align__(256) unsigned char g_wprep[12 * 32768];

// ---------------- helpers ----------------
// fast ELU: exp(x)-1 via ex2.approx (abs err ~2^-22, fine for 1e-3 budget)
__device__ __forceinline__ float elu1(float x) {
    float e;
    asm("ex2.approx.f32 %0, %1;" : "=f"(e) : "f"(x * 1.4426950408889634f));
    return x > 0.f ? x : (e - 1.0f);
}

__device__ __forceinline__ uint32_t smem_u32(const void* p) {
    uint32_t a;
    asm("{ .reg .u64 t; cvta.to.shared.u64 t, %1; cvt.u32.u64 %0, t; }" : "=r"(a) : "l"(p));
    return a;
}

#define CP_ASYNC16(dst, src) \
    asm volatile("cp.async.cg.shared.global [%0], [%1], 16;" :: "r"(dst), "l"(src))
#define CP_COMMIT() asm volatile("cp.async.commit_group;")
#define CP_WAIT0()  asm volatile("cp.async.wait_group 0;")
#define BARG(id) asm volatile("bar.sync %0, 128;" :: "r"(id) : "memory")

// truncation split: hi = a with low 16 bits zeroed (exact bf16), lo = bf16(a - hi)
__device__ __forceinline__ void split2t(float a, float b, uint32_t& hi, uint32_t& lo) {
    uint32_t ai = __float_as_uint(a), bi = __float_as_uint(b);
    hi = __byte_perm(ai, bi, 0x7632);  // {a.hi16 in low, b.hi16 in high}
    float la = a - __uint_as_float(ai & 0xFFFF0000u);
    float lb = b - __uint_as_float(bi & 0xFFFF0000u);
    asm("cvt.rn.bf16x2.f32 %0, %1, %2;" : "=r"(lo) : "f"(lb), "f"(la));
}

// split 8 fp32 -> bf16 hi/lo, 16B stores to padded tiles
__device__ __forceinline__ void split_store8(const float* v, unsigned char* Ah,
                                             unsigned char* Al, uint32_t off) {
    uint32_t hw[4], lw[4];
#pragma unroll
    for (int i = 0; i < 4; i++) split2t(v[2 * i], v[2 * i + 1], hw[i], lw[i]);
    *reinterpret_cast<uint4*>(Ah + off) = make_uint4(hw[0], hw[1], hw[2], hw[3]);
    *reinterpret_cast<uint4*>(Al + off) = make_uint4(lw[0], lw[1], lw[2], lw[3]);
}

__device__ __forceinline__ void ldm4(uint32_t* r, uint32_t a) {
    asm volatile("ldmatrix.sync.aligned.m8n8.x4.shared.b16 {%0,%1,%2,%3}, [%4];"
                 : "=r"(r[0]), "=r"(r[1]), "=r"(r[2]), "=r"(r[3]) : "r"(a));
}

__device__ __forceinline__ void mma16816(float* c, const uint32_t* a, const uint32_t* b) {
    asm volatile(
        "mma.sync.aligned.m16n8k16.row.col.f32.bf16.bf16.f32 "
        "{%0,%1,%2,%3}, {%4,%5,%6,%7}, {%8,%9}, {%0,%1,%2,%3};"
        : "+f"(c[0]), "+f"(c[1]), "+f"(c[2]), "+f"(c[3])
        : "r"(a[0]), "r"(a[1]), "r"(a[2]), "r"(a[3]), "r"(b[0]), "r"(b[1]));
}

// fused 3-split warp GEMM, k-outer, warp tile m32 x n32 (16 warps cover 128x128)
__device__ __forceinline__ void warp_gemm3(uint32_t Ah, uint32_t Al,
                                           uint32_t Wh, uint32_t Wl,
                                           int lane, int wm, int wn,
                                           float acc[2][4][4]) {
    const int arow = lane & 15;
    const int kA = ((lane >> 4) << 3) * 2;               // byte k-offset
    const int brow = ((lane >> 4) << 3) + (lane & 7);
    const int kB = (((lane >> 3) & 1) << 3) * 2;
    const uint32_t aoff0 = (uint32_t)((wm * 32 + arow) * TILE_PITCH) + kA;
    const uint32_t aoff1 = aoff0 + 16 * TILE_PITCH;
    uint32_t boff[2];
#pragma unroll
    for (int p = 0; p < 2; p++)
        boff[p] = (uint32_t)((wn * 32 + p * 16 + brow) * TILE_PITCH) + kB;

#pragma unroll
    for (int k0 = 0; k0 < 128; k0 += 16) {
        uint32_t ah0[4], ah1[4], al0[4], al1[4], bh[2][4], bl[2][4];
        ldm4(ah0, Ah + aoff0 + k0 * 2);
        ldm4(ah1, Ah + aoff1 + k0 * 2);
        ldm4(al0, Al + aoff0 + k0 * 2);
        ldm4(al1, Al + aoff1 + k0 * 2);
#pragma unroll
        for (int p = 0; p < 2; p++) ldm4(bh[p], Wh + boff[p] + k0 * 2);
#pragma unroll
        for (int p = 0; p < 2; p++) ldm4(bl[p], Wl + boff[p] + k0 * 2);
#pragma unroll
        for (int j = 0; j < 4; j++) {
            const uint32_t* bhj = &bh[j >> 1][(j & 1) * 2];
            mma16816(acc[0][j], ah0, bhj);
            mma16816(acc[1][j], ah1, bhj);
        }
#pragma unroll
        for (int j = 0; j < 4; j++) {
            const uint32_t* bhj = &bh[j >> 1][(j & 1) * 2];
            mma16816(acc[0][j], al0, bhj);
            mma16816(acc[1][j], al1, bhj);
        }
#pragma unroll
        for (int j = 0; j < 4; j++) {
            const uint32_t* blj = &bl[j >> 1][(j & 1) * 2];
            mma16816(acc[0][j], ah0, blj);
            mma16816(acc[1][j], ah1, blj);
        }
    }
}

// ---------------- weight prep: transpose + bf16 split ----------------
// m: 0:W1s[0] 1:W2s[0] 2:W1s[1] 3:W2s[1] 4:eW1[0:128,:] 5:eW2
__global__ void prep_weights(const float* __restrict__ W1s, const float* __restrict__ W2s,
                             const float* __restrict__ eW1, const float* __restrict__ eW2)
{
    int idx = blockIdx.x * 256 + threadIdx.x;
    if (idx >= 6 * 16384) return;
    int m = idx >> 14;
    int e = idx & 16383;
    int n = e >> 7, k = e & 127;
    const float* W;
    switch (m) {
        case 0: W = W1s; break;
        case 1: W = W2s; break;
        case 2: W = W1s + 16384; break;
        case 3: W = W2s + 16384; break;
        case 4: W = eW1; break;
        default: W = eW2; break;
    }
    float v = W[k * 128 + n];
    __nv_bfloat16 h = __float2bfloat16(v);
    __nv_bfloat16 l = __float2bfloat16(v - __bfloat162float(h));
    *reinterpret_cast<__nv_bfloat16*>(g_wprep + (size_t)(2 * m) * 32768 + (size_t)e * 2) = h;
    *reinterpret_cast<__nv_bfloat16*>(g_wprep + (size_t)(2 * m + 1) * 32768 + (size_t)e * 2) = l;
}

// ---------------- tensor-core fused MLP, 512 threads, 4 pipelined groups ----
template <bool GATHER>
__global__ void __launch_bounds__(512, 1)
tc_mlp_tpl(const float* __restrict__ X, int m1, int m2,
           const float* __restrict__ B1, const float* __restrict__ B2,
           float* __restrict__ out, int nrows, int mode, int stage,
           const float* __restrict__ preA, const float* __restrict__ preC,
           const int* __restrict__ srcI, const int* __restrict__ dstI)
{
    extern __shared__ unsigned char smem[];
    unsigned char* Ah  = smem;
    unsigned char* Al  = smem + TILE_BYTES_PAD;
    unsigned char* W1h = smem + 2 * TILE_BYTES_PAD;
    unsigned char* W1l = smem + 3 * TILE_BYTES_PAD;
    unsigned char* W2h = smem + 4 * TILE_BYTES_PAD;
    unsigned char* W2l = smem + 5 * TILE_BYTES_PAD;
    __shared__ float sB1[128], sB2[128], sPA[128], sPC[128];
    __shared__ float sSum[128], sSq[128];
    __shared__ int sSrc[128], sDst[128];

    const int tid = threadIdx.x, wid = tid >> 5, lane = tid & 31;
    const int wm = wid & 3, wn = wid >> 2;   // group = wm (4 warps, rows 32*wm)
    const int g = lane >> 2, tig = lane & 3;
    const int row0 = blockIdx.x * 128;

    // ---- async W1 + W2 prefetch ----
    {
        const char* g1 = (const char*)(g_wprep + (size_t)(2 * m1) * 32768);
        const char* g2 = (const char*)(g_wprep + (size_t)(2 * m2) * 32768);
#pragma unroll
        for (int t = 0; t < 4; t++) {
            int idx = tid + 512 * t;
            uint32_t off = (uint32_t)((idx >> 4) * TILE_PITCH + (idx & 15) * 16);
            CP_ASYNC16(smem_u32(W1h + off), g1 + (size_t)idx * 16);
            CP_ASYNC16(smem_u32(W1l + off), g1 + 32768 + (size_t)idx * 16);
            CP_ASYNC16(smem_u32(W2h + off), g2 + (size_t)idx * 16);
            CP_ASYNC16(smem_u32(W2l + off), g2 + 32768 + (size_t)idx * 16);
        }
        CP_COMMIT();
    }

    if (tid < 128) {
        sB1[tid] = B1[tid];
        sB2[tid] = B2[tid];
        sSum[tid] = 0.f; sSq[tid] = 0.f;
        if (mode == 1) { sPA[tid] = preA[tid]; sPC[tid] = preC[tid]; }
        if (GATHER) {
            int gr = row0 + tid;
            sSrc[tid] = (gr < nrows) ? srcI[gr] : 0;
            sDst[tid] = (gr < nrows) ? dstI[gr] : 0;
        }
    }
    // mode==1 needs sPA/sPC for the A-load below -> full barrier first
    __syncthreads();

    // ---- per-group A load + split: group wm owns rows [wm*32, wm*32+32) ----
    {
        int gt = wn * 32 + lane;  // 0..127 within group
#pragma unroll
        for (int t = 0; t < 4; t++) {
            int r = wm * 32 + t * 8 + (gt >> 4);
            int kp = (gt & 15) << 3;
            int gr = row0 + r;
            float v[8];
            if (gr < nrows) {
                float4 a = *reinterpret_cast<const float4*>(X + (size_t)gr * D + kp);
                float4 b = *reinterpret_cast<const float4*>(X + (size_t)gr * D + kp + 4);
                v[0] = a.x; v[1] = a.y; v[2] = a.z; v[3] = a.w;
                v[4] = b.x; v[5] = b.y; v[6] = b.z; v[7] = b.w;
                if (mode == 1) {
#pragma unroll
                    for (int i = 0; i < 8; i++) v[i] = v[i] * sPA[kp + i] + sPC[kp + i];
                }
            } else {
#pragma unroll
                for (int i = 0; i < 8; i++) v[i] = 0.f;
            }
            split_store8(v, Ah, Al, (uint32_t)(r * TILE_PITCH + kp * 2));
        }
    }
    CP_WAIT0();        // this thread's W copies done
    __syncthreads();   // ALL W copies + A tiles visible; groups decouple after this

    const uint32_t uAh = smem_u32(Ah), uAl = smem_u32(Al);

    // ---- GEMM1 ----
    float acc[2][4][4];
#pragma unroll
    for (int i = 0; i < 2; i++)
#pragma unroll
        for (int j = 0; j < 4; j++) {
            int col = wn * 32 + j * 8 + 2 * tig;
            acc[i][j][0] = sB1[col]; acc[i][j][1] = sB1[col + 1];
            acc[i][j][2] = sB1[col]; acc[i][j][3] = sB1[col + 1];
        }
    warp_gemm3(uAh, uAl, smem_u32(W1h), smem_u32(W1l), lane, wm, wn, acc);
    BARG(wm + 1);      // group's 4 warps done reading group's A rows

    // ---- epilogue1: h1 = elu(acc [+ P1[src]+P2[dst]]); re-split into A ----
#pragma unroll
    for (int i = 0; i < 2; i++) {
        int r0 = wm * 32 + i * 16 + g;
        int r1 = r0 + 8;
#pragma unroll
        for (int j = 0; j < 4; j++) {
            int col = wn * 32 + j * 8 + 2 * tig;
            float v0 = acc[i][j][0], v1 = acc[i][j][1];
            float v2 = acc[i][j][2], v3 = acc[i][j][3];
            if (GATHER) {
                const float2 p1a = *reinterpret_cast<const float2*>(g_P1 + (size_t)sSrc[r0] * D + col);
                const float2 p2a = *reinterpret_cast<const float2*>(g_P2 + (size_t)sDst[r0] * D + col);
                const float2 p1b = *reinterpret_cast<const float2*>(g_P1 + (size_t)sSrc[r1] * D + col);
                const float2 p2b = *reinterpret_cast<const float2*>(g_P2 + (size_t)sDst[r1] * D + col);
                v0 += p1a.x + p2a.x; v1 += p1a.y + p2a.y;
                v2 += p1b.x + p2b.x; v3 += p1b.y + p2b.y;
            }
            v0 = elu1(v0); v1 = elu1(v1); v2 = elu1(v2); v3 = elu1(v3);
            uint32_t hi, lo;
            split2t(v0, v1, hi, lo);
            *reinterpret_cast<uint32_t*>(Ah + r0 * TILE_PITCH + col * 2) = hi;
            *reinterpret_cast<uint32_t*>(Al + r0 * TILE_PITCH + col * 2) = lo;
            split2t(v2, v3, hi, lo);
            *reinterpret_cast<uint32_t*>(Ah + r1 * TILE_PITCH + col * 2) = hi;
            *reinterpret_cast<uint32_t*>(Al + r1 * TILE_PITCH + col * 2) = lo;
        }
    }
    BARG(wm + 1);      // group's h1 tile complete

    // ---- GEMM2 ----
#pragma unroll
    for (int i = 0; i < 2; i++)
#pragma unroll
        for (int j = 0; j < 4; j++) {
            int col = wn * 32 + j * 8 + 2 * tig;
            acc[i][j][0] = sB2[col]; acc[i][j][1] = sB2[col + 1];
            acc[i][j][2] = sB2[col]; acc[i][j][3] = sB2[col + 1];
        }
    warp_gemm3(uAh, uAl, smem_u32(W2h), smem_u32(W2l), lane, wm, wn, acc);

    // ---- epilogue2: h2 = elu(acc) -> gmem; stats via shuffle + shared atomics
    float sc[4][2], sq[4][2];
#pragma unroll
    for (int j = 0; j < 4; j++) {
        sc[j][0] = sc[j][1] = 0.f;
        sq[j][0] = sq[j][1] = 0.f;
    }
#pragma unroll
    for (int i = 0; i < 2; i++) {
        int r0 = wm * 32 + i * 16 + g;
        int r1 = r0 + 8;
        int gr0 = row0 + r0, gr1 = row0 + r1;
        bool va = gr0 < nrows, vb = gr1 < nrows;
#pragma unroll
        for (int j = 0; j < 4; j++) {
            int col = wn * 32 + j * 8 + 2 * tig;
            float v0 = va ? elu1(acc[i][j][0]) : 0.f;
            float v1 = va ? elu1(acc[i][j][1]) : 0.f;
            float v2 = vb ? elu1(acc[i][j][2]) : 0.f;
            float v3 = vb ? elu1(acc[i][j][3]) : 0.f;
            sc[j][0] += v0 + v2; sc[j][1] += v1 + v3;
            sq[j][0] += v0 * v0 + v2 * v2; sq[j][1] += v1 * v1 + v3 * v3;
            if (va) *reinterpret_cast<float2*>(out + (size_t)gr0 * D + col) = make_float2(v0, v1);
            if (vb) *reinterpret_cast<float2*>(out + (size_t)gr1 * D + col) = make_float2(v2, v3);
        }
    }
    // butterfly over g (lanes differing in bits 2..4)
#pragma unroll
    for (int m = 4; m <= 16; m <<= 1)
#pragma unroll
        for (int j = 0; j < 4; j++)
#pragma unroll
            for (int k = 0; k < 2; k++) {
                sc[j][k] += __shfl_xor_sync(0xFFFFFFFFu, sc[j][k], m);
                sq[j][k] += __shfl_xor_sync(0xFFFFFFFFu, sq[j][k], m);
            }
    if (lane < 4) {
#pragma unroll
        for (int j = 0; j < 4; j++) {
            int col = wn * 32 + j * 8 + 2 * lane;
            atomicAdd(&sSum[col], sc[j][0]);
            atomicAdd(&sSum[col + 1], sc[j][1]);
            atomicAdd(&sSq[col], sq[j][0]);
            atomicAdd(&sSq[col + 1], sq[j][1]);
        }
    }
    __syncthreads();
    if (tid < 128) {
        atomicAdd(&g_stats[stage * 256 + tid], sSum[tid]);
        atomicAdd(&g_stats[stage * 256 + 128 + tid], sSq[tid]);
    }
}

// ---------------- SIMT path for small node stages ----------------
__device__ __forceinline__ float2 ffma2(float2 d, float2 a, float2 b) {
    asm("fma.rn.f32x2 %0, %1, %2, %0;"
        : "+l"(reinterpret_cast<unsigned long long&>(d))
        : "l"(reinterpret_cast<unsigned long long&>(a)),
          "l"(reinterpret_cast<unsigned long long&>(b)));
    return d;
}

__device__ __forceinline__ void gemm_tile(const float* __restrict__ Xs,
                                          const float* __restrict__ Ws,
                                          float2 acc[8][4], int tx, int ty) {
#pragma unroll 2
    for (int k = 0; k < 128; k++) {
        float xv[8];
        float2 ww[4];
#pragma unroll
        for (int j = 0; j < 8; j++) xv[j] = Xs[(ty + 16 * j) * PADX + k];
#pragma unroll
        for (int p = 0; p < 4; p++) {
            float w0 = Ws[k * 128 + tx + 32 * p];
            float w1 = Ws[k * 128 + tx + 32 * p + 16];
            ww[p] = make_float2(w0, w1);
        }
#pragma unroll
        for (int j = 0; j < 8; j++) {
            float2 xx = make_float2(xv[j], xv[j]);
#pragma unroll
            for (int p = 0; p < 4; p++) acc[j][p] = ffma2(acc[j][p], xx, ww[p]);
        }
    }
}

__global__ void __launch_bounds__(256, 1)
mlp_kernel(const float* __restrict__ X,
           const float* __restrict__ W1, const float* __restrict__ B1,
           const float* __restrict__ W2, const float* __restrict__ B2,
           float* __restrict__ out, int nrows, int mode, int stage,
           const float* __restrict__ preA, const float* __restrict__ preC,
           const float* __restrict__ degp)
{
    extern __shared__ float smemf[];
    float* Xs = smemf;
    float* Ws = smemf + 128 * PADX;
    __shared__ float sB[128];
    __shared__ float sPA[128], sPC[128], sDeg[128];

    const int tid = threadIdx.x;
    const int tx = tid & 15, ty = tid >> 4;
    const int row0 = blockIdx.x * 128;

    if (tid < 128) {
        sB[tid] = B1[tid];
        if (mode == 1) { sPA[tid] = preA[tid]; sPC[tid] = preC[tid]; }
        if (mode == 2) {
            int r = row0 + tid;
            sDeg[tid] = (r < nrows) ? (1.f / fmaxf(degp[r], 1.f)) : 0.f;
        }
    }
    __syncthreads();

#pragma unroll
    for (int t = 0; t < 16; t++) {
        int idx = tid + t * 256;
        int r = idx >> 5;
        int c4 = (idx & 31) << 2;
        int gr = row0 + r;
        float4 v = make_float4(0.f, 0.f, 0.f, 0.f);
        if (gr < nrows) {
            v = *reinterpret_cast<const float4*>(X + (size_t)gr * D + c4);
            if (mode == 1) {
                v.x = v.x * sPA[c4] + sPC[c4];
                v.y = v.y * sPA[c4 + 1] + sPC[c4 + 1];
                v.z = v.z * sPA[c4 + 2] + sPC[c4 + 2];
                v.w = v.w * sPA[c4 + 3] + sPC[c4 + 3];
            } else if (mode == 2) {
                float s = sDeg[r];
                v.x *= s; v.y *= s; v.z *= s; v.w *= s;
            }
        }
        *reinterpret_cast<float4*>(Xs + r * PADX + c4) = v;
        reinterpret_cast<float4*>(Ws)[idx] = reinterpret_cast<const float4*>(W1)[idx];
    }
    __syncthreads();

    float2 acc[8][4];
#pragma unroll
    for (int j = 0; j < 8; j++)
#pragma unroll
        for (int p = 0; p < 4; p++)
            acc[j][p] = make_float2(sB[tx + 32 * p], sB[tx + 32 * p + 16]);

    gemm_tile(Xs, Ws, acc, tx, ty);
#pragma unroll
    for (int j = 0; j < 8; j++)
#pragma unroll
        for (int p = 0; p < 4; p++) {
            acc[j][p].x = elu1(acc[j][p].x);
            acc[j][p].y = elu1(acc[j][p].y);
        }
    __syncthreads();

#pragma unroll
    for (int j = 0; j < 8; j++) {
        int r = ty + 16 * j;
#pragma unroll
        for (int p = 0; p < 4; p++) {
            Xs[r * PADX + tx + 32 * p]      = acc[j][p].x;
            Xs[r * PADX + tx + 32 * p + 16] = acc[j][p].y;
        }
    }
#pragma unroll
    for (int t = 0; t < 16; t++) {
        int idx = tid + t * 256;
        reinterpret_cast<float4*>(Ws)[idx] = reinterpret_cast<const float4*>(W2)[idx];
    }
    if (tid < 128) sB[tid] = B2[tid];
    __syncthreads();

#pragma unroll
    for (int j = 0; j < 8; j++)
#pragma unroll
        for (int p = 0; p < 4; p++)
            acc[j][p] = make_float2(sB[tx + 32 * p], sB[tx + 32 * p + 16]);

    gemm_tile(Xs, Ws, acc, tx, ty);
#pragma unroll
    for (int j = 0; j < 8; j++)
#pragma unroll
        for (int p = 0; p < 4; p++) {
            acc[j][p].x = elu1(acc[j][p].x);
            acc[j][p].y = elu1(acc[j][p].y);
        }
    __syncthreads();

#pragma unroll
    for (int j = 0; j < 8; j++) {
        int r = ty + 16 * j;
        int gr = row0 + r;
        bool valid = gr < nrows;
#pragma unroll
        for (int p = 0; p < 4; p++) {
            int c0 = tx + 32 * p, c1 = c0 + 16;
            float vx = valid ? acc[j][p].x : 0.f;
            float vy = valid ? acc[j][p].y : 0.f;
            Xs[r * PADX + c0] = vx;
            Xs[r * PADX + c1] = vy;
            if (valid) {
                out[(size_t)gr * D + c0] = vx;
                out[(size_t)gr * D + c1] = vy;
            }
        }
    }
    __syncthreads();

    if (tid < 128) {
        float s = 0.f, q = 0.f;
#pragma unroll 4
        for (int r = 0; r < 128; r++) {
            float vv = Xs[r * PADX + tid];
            s += vv; q += vv * vv;
        }
        atomicAdd(&g_stats[stage * 256 + tid], s);
        atomicAdd(&g_stats[stage * 256 + 128 + tid], q);
    }
}

__global__ void finalize_bn(int stage, float cnt,
                            const float* __restrict__ g, const float* __restrict__ bt)
{
    int j = threadIdx.x;
    float s1 = g_stats[stage * 256 + j];
    float s2 = g_stats[stage * 256 + 128 + j];
    float mu = s1 / cnt;
    float var = s2 / cnt - mu * mu;
    float a = g[j] * rsqrtf(var + EPS);
    g_bnA[stage * 128 + j] = a;
    g_bnC[stage * 128 + j] = bt[j] - mu * a;
}

__global__ void __launch_bounds__(256)
scatter_kernel(const int* __restrict__ dst, int nedges)
{
    int lane = threadIdx.x & 31;
    int warp = (blockIdx.x * 256 + threadIdx.x) >> 5;
    int nw = (gridDim.x * 256) >> 5;
    float4 A0 = reinterpret_cast<const float4*>(g_bnA)[lane];
    float4 C0 = reinterpret_cast<const float4*>(g_bnC)[lane];
    float4 A1 = reinterpret_cast<const float4*>(g_bnA + 128)[lane];
    float4 C1 = reinterpret_cast<const float4*>(g_bnC + 128)[lane];
    for (int e = warp; e < nedges; e += nw) {
        int d = __ldg(dst + e);
        float4 t = reinterpret_cast<const float4*>(g_t1 + (size_t)e * D)[lane];
        float4 u = reinterpret_cast<const float4*>(g_u + (size_t)e * D)[lane];
        float4 h;
        h.x = (t.x * A0.x + C0.x) + (u.x * A1.x + C1.x);
        h.y = (t.y * A0.y + C0.y) + (u.y * A1.y + C1.y);
        h.z = (t.z * A0.z + C0.z) + (u.z * A1.z + C1.z);
        h.w = (t.w * A0.w + C0.w) + (u.w * A1.w + C1.w);
        float* base = g_agg + (size_t)d * D + lane * 4;
        asm volatile("red.global.add.v4.f32 [%0], {%1, %2, %3, %4};"
                     :: "l"(base), "f"(h.x), "f"(h.y), "f"(h.z), "f"(h.w)
                     : "memory");
        if (lane == 0) atomicAdd(&g_deg[d], 1.f);
    }
}

__global__ void __launch_bounds__(256, 1)
node_final_kernel(const float* __restrict__ eW1, int nrows)
{
    extern __shared__ float smemf[];
    float* Hs = smemf;
    float* Ws = smemf + 128 * PADX;
    const int tid = threadIdx.x;
    const int tx = tid & 15, ty = tid >> 4;
    const int row0 = blockIdx.x * 128;

#pragma unroll
    for (int t = 0; t < 16; t++) {
        int idx = tid + t * 256;
        int r = idx >> 5;
        int c4 = (idx & 31) << 2;
        int gr = row0 + r;
        float4 h = make_float4(0.f, 0.f, 0.f, 0.f);
        if (gr < nrows) {
            float4 v = *reinterpret_cast<const float4*>(g_v + (size_t)gr * D + c4);
            float4 w = *reinterpret_cast<const float4*>(g_w + (size_t)gr * D + c4);
            float4 A2 = reinterpret_cast<const float4*>(g_bnA + 256)[c4 >> 2];
            float4 C2 = reinterpret_cast<const float4*>(g_bnC + 256)[c4 >> 2];
            float4 A3 = reinterpret_cast<const float4*>(g_bnA + 384)[c4 >> 2];
            float4 C3 = reinterpret_cast<const float4*>(g_bnC + 384)[c4 >> 2];
            h.x = (w.x * A3.x + C3.x) + (v.x * A2.x + C2.x);
            h.y = (w.y * A3.y + C3.y) + (v.y * A2.y + C2.y);
            h.z = (w.z * A3.z + C3.z) + (v.z * A2.z + C2.z);
            h.w = (w.w * A3.w + C3.w) + (v.w * A2.w + C2.w);
        }
        *reinterpret_cast<float4*>(Hs + r * PADX + c4) = h;
        reinterpret_cast<float4*>(Ws)[idx] =
            reinterpret_cast<const float4*>(eW1 + 128 * 128)[idx];
    }
    __syncthreads();

    float2 acc[8][4];
#pragma unroll
    for (int j = 0; j < 8; j++)
#pragma unroll
        for (int p = 0; p < 4; p++) acc[j][p] = make_float2(0.f, 0.f);
    gemm_tile(Hs, Ws, acc, tx, ty);
    __syncthreads();

#pragma unroll
    for (int j = 0; j < 8; j++) {
        int gr = row0 + ty + 16 * j;
        if (gr < nrows)
#pragma unroll
            for (int p = 0; p < 4; p++) {
                g_P1[(size_t)gr * D + tx + 32 * p]      = acc[j][p].x;
                g_P1[(size_t)gr * D + tx + 32 * p + 16] = acc[j][p].y;
            }
    }
#pragma unroll
    for (int t = 0; t < 16; t++) {
        int idx = tid + t * 256;
        reinterpret_cast<float4*>(Ws)[idx] =
            reinterpret_cast<const float4*>(eW1 + 256 * 128)[idx];
    }
    __syncthreads();

#pragma unroll
    for (int j = 0; j < 8; j++)
#pragma unroll
        for (int p = 0; p < 4; p++) acc[j][p] = make_float2(0.f, 0.f);
    gemm_tile(Hs, Ws, acc, tx, ty);

#pragma unroll
    for (int j = 0; j < 8; j++) {
        int gr = row0 + ty + 16 * j;
        if (gr < nrows)
#pragma unroll
            for (int p = 0; p < 4; p++) {
                g_P2[(size_t)gr * D + tx + 32 * p]      = acc[j][p].x;
                g_P2[(size_t)gr * D + tx + 32 * p + 16] = acc[j][p].y;
            }
    }
}

__global__ void norm_out_kernel(float* __restrict__ out, int n4)
{
    int idx = blockIdx.x * blockDim.x + threadIdx.x;
    if (idx >= n4) return;
    int cv = idx & 31;
    float4 A = reinterpret_cast<const float4*>(g_bnA + 512)[cv];
    float4 C = reinterpret_cast<const float4*>(g_bnC + 512)[cv];
    float4 v = reinterpret_cast<float4*>(out)[idx];
    v.x = v.x * A.x + C.x;
    v.y = v.y * A.y + C.y;
    v.z = v.z * A.z + C.z;
    v.w = v.w * A.w + C.w;
    reinterpret_cast<float4*>(out)[idx] = v;
}

// ---------------- host orchestration ----------------
extern "C" void kernel_launch(void* const* d_in, const int* in_sizes, int n_in,
                              void* d_out, int out_size)
{
    if (n_in < 15) return;
    const float* edata = (const float*)d_in[0];
    const int*   src   = (const int*)d_in[1];
    const int*   dst   = (const int*)d_in[2];
    int w = (n_in >= 16) ? 4 : 3;
    const float* W1s = (const float*)d_in[w + 0];
    const float* b1s = (const float*)d_in[w + 1];
    const float* W2s = (const float*)d_in[w + 2];
    const float* b2s = (const float*)d_in[w + 3];
    const float* gs  = (const float*)d_in[w + 4];
    const float* bts = (const float*)d_in[w + 5];
    const float* eW1 = (const float*)d_in[w + 6];
    const float* eb1 = (const float*)d_in[w + 7];
    const float* eW2 = (const float*)d_in[w + 8];
    const float* eb2 = (const float*)d_in[w + 9];
    const float* eg  = (const float*)d_in[w + 10];
    const float* ebt = (const float*)d_in[w + 11];

    int E = in_sizes[0] / D;
    int N = 20000;

    float *p_t1, *p_u, *p_v, *p_w2, *p_agg, *p_deg, *p_stats, *p_bnA, *p_bnC;
    cudaGetSymbolAddress((void**)&p_t1, g_t1);
    cudaGetSymbolAddress((void**)&p_u, g_u);
    cudaGetSymbolAddress((void**)&p_v, g_v);
    cudaGetSymbolAddress((void**)&p_w2, g_w);
    cudaGetSymbolAddress((void**)&p_agg, g_agg);
    cudaGetSymbolAddress((void**)&p_deg, g_deg);
    cudaGetSymbolAddress((void**)&p_stats, g_stats);
    cudaGetSymbolAddress((void**)&p_bnA, g_bnA);
    cudaGetSymbolAddress((void**)&p_bnC, g_bnC);

    cudaFuncSetAttribute(mlp_kernel, cudaFuncAttributeMaxDynamicSharedMemorySize, SMEM_BYTES);
    cudaFuncSetAttribute(node_final_kernel, cudaFuncAttributeMaxDynamicSharedMemorySize, SMEM_BYTES);
    cudaFuncSetAttribute(tc_mlp_tpl<false>, cudaFuncAttributeMaxDynamicSharedMemorySize, TC_SMEM);
    cudaFuncSetAttribute(tc_mlp_tpl<true>,  cudaFuncAttributeMaxDynamicSharedMemorySize, TC_SMEM);

    cudaMemsetAsync(p_stats, 0, 5 * 2 * 128 * sizeof(float), 0);
    cudaMemsetAsync(p_agg, 0, (size_t)NODE_CAP * D * sizeof(float), 0);
    cudaMemsetAsync(p_deg, 0, NODE_CAP * sizeof(float), 0);

    int egrid = (E + 127) / 128;
    int ngrid = (N + 127) / 128;

    // weight prep: transpose + bf16 hi/lo split
    prep_weights<<<(6 * 16384 + 255) / 256, 256>>>(W1s, W2s, eW1, eW2);

    // edge MLP0 (tensor cores)
    tc_mlp_tpl<false><<<egrid, 512, TC_SMEM>>>(edata, 0, 1, b1s, b2s,
                                               p_t1, E, 0, 0, nullptr, nullptr,
                                               nullptr, nullptr);
    finalize_bn<<<1, 128>>>(0, (float)E, gs, bts);
    // edge MLP1 (input = BN0(t1), folded affine)
    tc_mlp_tpl<false><<<egrid, 512, TC_SMEM>>>(p_t1, 2, 3, b1s + 128, b2s + 128,
                                               p_u, E, 1, 1, p_bnA, p_bnC,
                                               nullptr, nullptr);
    finalize_bn<<<1, 128>>>(1, (float)E, gs + 128, bts + 128);
    // h_e = BN0(t1)+BN1(u); scatter-sum + degree
    scatter_kernel<<<2048, 256>>>(dst, E);
    // node MLP2 (input = agg / max(deg,1)) — SIMT
    mlp_kernel<<<ngrid, 256, SMEM_BYTES>>>(p_agg, W1s + 2 * 16384, b1s + 256,
                                           W2s + 2 * 16384, b2s + 256,
                                           p_v, N, 2, 2, nullptr, nullptr, p_deg);
    finalize_bn<<<1, 128>>>(2, (float)N, gs + 256, bts + 256);
    // node MLP3 — SIMT
    mlp_kernel<<<ngrid, 256, SMEM_BYTES>>>(p_v, W1s + 3 * 16384, b1s + 384,
                                           W2s + 3 * 16384, b2s + 384,
                                           p_w2, N, 1, 3, p_bnA + 256, p_bnC + 256, nullptr);
    finalize_bn<<<1, 128>>>(3, (float)N, gs + 384, bts + 384);
    // h_n + per-node partials P1/P2 through eW1 src/dst slices — SIMT
    node_final_kernel<<<ngrid, 256, SMEM_BYTES>>>(eW1, N);
    // final edge MLP (tensor cores, with gathers) -> d_out (pre-BN)
    tc_mlp_tpl<true><<<egrid, 512, TC_SMEM>>>(edata, 4, 5, eb1, eb2,
                                              (float*)d_out, E, 0, 4, nullptr, nullptr,
                                              src, dst);
    finalize_bn<<<1, 128>>>(4, (float)E, eg, ebt);
    int n4 = E * (D / 4);
    norm_out_kernel<<<(n4 + 255) / 256, 256>>>((float*)d_out, n4);
}

// round 9
// speedup vs baseline: 1.0070x; 1.0070x over previous
#include <cuda_runtime.h>
#include <cuda_bf16.h>
#include <math.h>
#include <stdint.h>

#define D 128
#define EPS 1e-5f
#define PADX 132
#define NODE_CAP 20096
#define E_MAX 640000

static const int SMEM_BYTES = (128 * PADX + 128 * 128) * 4;  // SIMT kernels
// TC kernel smem: 6 tiles (Ah, Al, W1h, W1l, W2h, W2l), 128 rows x 272 bytes
#define TILE_PITCH 272
#define TILE_BYTES_PAD (128 * TILE_PITCH)  // 34816
static const int TC_SMEM = 6 * TILE_BYTES_PAD;  // 208896

// ---------------- scratch ----------------
__device__ float g_t1[(size_t)E_MAX * D];
__device__ float g_u [(size_t)E_MAX * D];
__device__ float g_v [(size_t)NODE_CAP * D];
__device__ float g_w [(size_t)NODE_CAP * D];
__device__ float g_P1[(size_t)NODE_CAP * D];
__device__ float g_P2[(size_t)NODE_CAP * D];
__device__ float g_agg[(size_t)NODE_CAP * D];
__device__ float g_deg[NODE_CAP];
__device__ float g_stats[5 * 2 * 128];
// prepped weights: 6 matrices x (hi,lo), each [n][k] bf16 128x128 = 32KB
__device__ __align__(256) unsigned char g_wprep[12 * 32768];

// ---------------- helpers ----------------
// fast ELU: exp(x)-1 via ex2.approx (abs err ~2^-22, fine for 1e-3 budget)
__device__ __forceinline__ float elu1(float x) {
    float e;
    asm("ex2.approx.f32 %0, %1;" : "=f"(e) : "f"(x * 1.4426950408889634f));
    return x > 0.f ? x : (e - 1.0f);
}

__device__ __forceinline__ uint32_t smem_u32(const void* p) {
    uint32_t a;
    asm("{ .reg .u64 t; cvta.to.shared.u64 t, %1; cvt.u32.u64 %0, t; }" : "=r"(a) : "l"(p));
    return a;
}

#define CP_ASYNC16(dst, src) \
    asm volatile("cp.async.cg.shared.global [%0], [%1], 16;" :: "r"(dst), "l"(src))
#define CP_COMMIT() asm volatile("cp.async.commit_group;")
#define CP_WAIT1()  asm volatile("cp.async.wait_group 1;")
#define CP_WAIT0()  asm volatile("cp.async.wait_group 0;")

// compute folded BN coeffs for one stage into smem (call with tid<128, then sync)
__device__ __forceinline__ void bn_coeff(int stage, float cnt,
                                         const float* __restrict__ gv,
                                         const float* __restrict__ btv,
                                         int j, float& A, float& C) {
    float s1 = g_stats[stage * 256 + j];
    float s2 = g_stats[stage * 256 + 128 + j];
    float mu = s1 / cnt;
    float var = s2 / cnt - mu * mu;
    A = gv[j] * rsqrtf(var + EPS);
    C = btv[j] - mu * A;
}

// truncation split: hi = a with low 16 bits zeroed (exact bf16), lo = bf16(a - hi)
__device__ __forceinline__ void split2t(float a, float b, uint32_t& hi, uint32_t& lo) {
    uint32_t ai = __float_as_uint(a), bi = __float_as_uint(b);
    hi = __byte_perm(ai, bi, 0x7632);  // {a.hi16 in low, b.hi16 in high}
    float la = a - __uint_as_float(ai & 0xFFFF0000u);
    float lb = b - __uint_as_float(bi & 0xFFFF0000u);
    asm("cvt.rn.bf16x2.f32 %0, %1, %2;" : "=r"(lo) : "f"(lb), "f"(la));
}

// split 8 fp32 -> bf16 hi/lo, 16B stores to padded tiles
__device__ __forceinline__ void split_store8(const float* v, unsigned char* Ah,
                                             unsigned char* Al, uint32_t off) {
    uint32_t hw[4], lw[4];
#pragma unroll
    for (int i = 0; i < 4; i++) split2t(v[2 * i], v[2 * i + 1], hw[i], lw[i]);
    *reinterpret_cast<uint4*>(Ah + off) = make_uint4(hw[0], hw[1], hw[2], hw[3]);
    *reinterpret_cast<uint4*>(Al + off) = make_uint4(lw[0], lw[1], lw[2], lw[3]);
}

__device__ __forceinline__ void ldm4(uint32_t* r, uint32_t a) {
    asm volatile("ldmatrix.sync.aligned.m8n8.x4.shared.b16 {%0,%1,%2,%3}, [%4];"
                 : "=r"(r[0]), "=r"(r[1]), "=r"(r[2]), "=r"(r[3]) : "r"(a));
}

__device__ __forceinline__ void mma16816(float* c, const uint32_t* a, const uint32_t* b) {
    asm volatile(
        "mma.sync.aligned.m16n8k16.row.col.f32.bf16.bf16.f32 "
        "{%0,%1,%2,%3}, {%4,%5,%6,%7}, {%8,%9}, {%0,%1,%2,%3};"
        : "+f"(c[0]), "+f"(c[1]), "+f"(c[2]), "+f"(c[3])
        : "r"(a[0]), "r"(a[1]), "r"(a[2]), "r"(a[3]), "r"(b[0]), "r"(b[1]));
}

// fused 3-split warp GEMM, k-outer, warp tile m32 x n32 (16 warps cover 128x128)
__device__ __forceinline__ void warp_gemm3(uint32_t Ah, uint32_t Al,
                                           uint32_t Wh, uint32_t Wl,
                                           int lane, int wm, int wn,
                                           float acc[2][4][4]) {
    const int arow = lane & 15;
    const int kA = ((lane >> 4) << 3) * 2;               // byte k-offset
    const int brow = ((lane >> 4) << 3) + (lane & 7);
    const int kB = (((lane >> 3) & 1) << 3) * 2;
    const uint32_t aoff0 = (uint32_t)((wm * 32 + arow) * TILE_PITCH) + kA;
    const uint32_t aoff1 = aoff0 + 16 * TILE_PITCH;
    uint32_t boff[2];
#pragma unroll
    for (int p = 0; p < 2; p++)
        boff[p] = (uint32_t)((wn * 32 + p * 16 + brow) * TILE_PITCH) + kB;

#pragma unroll
    for (int k0 = 0; k0 < 128; k0 += 16) {
        uint32_t ah0[4], ah1[4], al0[4], al1[4], bh[2][4], bl[2][4];
        ldm4(ah0, Ah + aoff0 + k0 * 2);
        ldm4(ah1, Ah + aoff1 + k0 * 2);
        ldm4(al0, Al + aoff0 + k0 * 2);
        ldm4(al1, Al + aoff1 + k0 * 2);
#pragma unroll
        for (int p = 0; p < 2; p++) ldm4(bh[p], Wh + boff[p] + k0 * 2);
#pragma unroll
        for (int p = 0; p < 2; p++) ldm4(bl[p], Wl + boff[p] + k0 * 2);
#pragma unroll
        for (int j = 0; j < 4; j++) {
            const uint32_t* bhj = &bh[j >> 1][(j & 1) * 2];
            mma16816(acc[0][j], ah0, bhj);
            mma16816(acc[1][j], ah1, bhj);
        }
#pragma unroll
        for (int j = 0; j < 4; j++) {
            const uint32_t* bhj = &bh[j >> 1][(j & 1) * 2];
            mma16816(acc[0][j], al0, bhj);
            mma16816(acc[1][j], al1, bhj);
        }
#pragma unroll
        for (int j = 0; j < 4; j++) {
            const uint32_t* blj = &bl[j >> 1][(j & 1) * 2];
            mma16816(acc[0][j], ah0, blj);
            mma16816(acc[1][j], ah1, blj);
        }
    }
}

// ---------------- weight prep: transpose + bf16 split (+ zero stats) -------
// m: 0:W1s[0] 1:W2s[0] 2:W1s[1] 3:W2s[1] 4:eW1[0:128,:] 5:eW2
__global__ void prep_weights(const float* __restrict__ W1s, const float* __restrict__ W2s,
                             const float* __restrict__ eW1, const float* __restrict__ eW2)
{
    if (blockIdx.x == 0) {
        for (int i = threadIdx.x; i < 5 * 2 * 128; i += 256) g_stats[i] = 0.f;
    }
    int idx = blockIdx.x * 256 + threadIdx.x;
    if (idx >= 6 * 16384) return;
    int m = idx >> 14;
    int e = idx & 16383;
    int n = e >> 7, k = e & 127;
    const float* W;
    switch (m) {
        case 0: W = W1s; break;
        case 1: W = W2s; break;
        case 2: W = W1s + 16384; break;
        case 3: W = W2s + 16384; break;
        case 4: W = eW1; break;
        default: W = eW2; break;
    }
    float v = W[k * 128 + n];
    __nv_bfloat16 h = __float2bfloat16(v);
    __nv_bfloat16 l = __float2bfloat16(v - __bfloat162float(h));
    *reinterpret_cast<__nv_bfloat16*>(g_wprep + (size_t)(2 * m) * 32768 + (size_t)e * 2) = h;
    *reinterpret_cast<__nv_bfloat16*>(g_wprep + (size_t)(2 * m + 1) * 32768 + (size_t)e * 2) = l;
}

// ---------------- tensor-core fused MLP over 128-row tiles, 512 threads ----
// mode 0: raw X.  mode 1: X*BN(prev_stage) folded (coeffs computed in-kernel).
template <bool GATHER>
__global__ void __launch_bounds__(512, 1)
tc_mlp_tpl(const float* __restrict__ X, int m1, int m2,
           const float* __restrict__ B1, const float* __restrict__ B2,
           float* __restrict__ out, int nrows, int mode, int stage,
           const float* __restrict__ gprev, const float* __restrict__ btprev,
           float cntprev,
           const int* __restrict__ srcI, const int* __restrict__ dstI)
{
    extern __shared__ unsigned char smem[];
    unsigned char* Ah  = smem;
    unsigned char* Al  = smem + TILE_BYTES_PAD;
    unsigned char* W1h = smem + 2 * TILE_BYTES_PAD;
    unsigned char* W1l = smem + 3 * TILE_BYTES_PAD;
    unsigned char* W2h = smem + 4 * TILE_BYTES_PAD;
    unsigned char* W2l = smem + 5 * TILE_BYTES_PAD;
    __shared__ float sB1[128], sB2[128], sPA[128], sPC[128];
    __shared__ int sSrc[128], sDst[128];

    const int tid = threadIdx.x, wid = tid >> 5, lane = tid & 31;
    const int wm = wid & 3, wn = wid >> 2;       // warp tile: rows 32*wm, cols 32*wn
    const int g = lane >> 2, tig = lane & 3;
    const int row0 = blockIdx.x * 128;

    // ---- async W1 prefetch (group old), W2 prefetch (group young) ----
    {
        const char* g1 = (const char*)(g_wprep + (size_t)(2 * m1) * 32768);
        const char* g2 = (const char*)(g_wprep + (size_t)(2 * m2) * 32768);
#pragma unroll
        for (int t = 0; t < 4; t++) {
            int idx = tid + 512 * t;
            uint32_t off = (uint32_t)((idx >> 4) * TILE_PITCH + (idx & 15) * 16);
            CP_ASYNC16(smem_u32(W1h + off), g1 + (size_t)idx * 16);
            CP_ASYNC16(smem_u32(W1l + off), g1 + 32768 + (size_t)idx * 16);
        }
        CP_COMMIT();
#pragma unroll
        for (int t = 0; t < 4; t++) {
            int idx = tid + 512 * t;
            uint32_t off = (uint32_t)((idx >> 4) * TILE_PITCH + (idx & 15) * 16);
            CP_ASYNC16(smem_u32(W2h + off), g2 + (size_t)idx * 16);
            CP_ASYNC16(smem_u32(W2l + off), g2 + 32768 + (size_t)idx * 16);
        }
        CP_COMMIT();
    }

    if (tid < 128) {
        sB1[tid] = B1[tid];
        sB2[tid] = B2[tid];
        if (mode == 1) {
            float A, C;
            bn_coeff(stage - 1, cntprev, gprev, btprev, tid, A, C);
            sPA[tid] = A; sPC[tid] = C;
        }
        if (GATHER) {
            int gr = row0 + tid;
            sSrc[tid] = (gr < nrows) ? srcI[gr] : 0;
            sDst[tid] = (gr < nrows) ? dstI[gr] : 0;
        }
    }
    __syncthreads();  // sPA/sPC visible before A-load uses them

    // ---- coalesced load + split A tile (8-float groups, lane-contiguous) ----
#pragma unroll
    for (int t = 0; t < 4; t++) {
        int q = tid + 512 * t;        // 2048 groups of 8 floats
        int r = q >> 4;
        int kp = (q & 15) << 3;
        int gr = row0 + r;
        float v[8];
        if (gr < nrows) {
            float4 a = *reinterpret_cast<const float4*>(X + (size_t)gr * D + kp);
            float4 b = *reinterpret_cast<const float4*>(X + (size_t)gr * D + kp + 4);
            v[0] = a.x; v[1] = a.y; v[2] = a.z; v[3] = a.w;
            v[4] = b.x; v[5] = b.y; v[6] = b.z; v[7] = b.w;
            if (mode == 1) {
#pragma unroll
                for (int i = 0; i < 8; i++) v[i] = v[i] * sPA[kp + i] + sPC[kp + i];
            }
        } else {
#pragma unroll
            for (int i = 0; i < 8; i++) v[i] = 0.f;
        }
        split_store8(v, Ah, Al, (uint32_t)(r * TILE_PITCH + kp * 2));
    }
    CP_WAIT1();       // W1 resident
    __syncthreads();

    const uint32_t uAh = smem_u32(Ah), uAl = smem_u32(Al);

    // ---- GEMM1 ----
    float acc[2][4][4];
#pragma unroll
    for (int i = 0; i < 2; i++)
#pragma unroll
        for (int j = 0; j < 4; j++) {
            int col = wn * 32 + j * 8 + 2 * tig;
            acc[i][j][0] = sB1[col]; acc[i][j][1] = sB1[col + 1];
            acc[i][j][2] = sB1[col]; acc[i][j][3] = sB1[col + 1];
        }
    warp_gemm3(uAh, uAl, smem_u32(W1h), smem_u32(W1l), lane, wm, wn, acc);
    __syncthreads();  // all warps done reading Ah/Al before rewrite

    // ---- epilogue1: h1 = elu(acc [+ P1[src]+P2[dst]]); re-split into A ----
#pragma unroll
    for (int i = 0; i < 2; i++) {
        int r0 = wm * 32 + i * 16 + g;
        int r1 = r0 + 8;
#pragma unroll
        for (int j = 0; j < 4; j++) {
            int col = wn * 32 + j * 8 + 2 * tig;
            float v0 = acc[i][j][0], v1 = acc[i][j][1];
            float v2 = acc[i][j][2], v3 = acc[i][j][3];
            if (GATHER) {
                const float2 p1a = *reinterpret_cast<const float2*>(g_P1 + (size_t)sSrc[r0] * D + col);
                const float2 p2a = *reinterpret_cast<const float2*>(g_P2 + (size_t)sDst[r0] * D + col);
                const float2 p1b = *reinterpret_cast<const float2*>(g_P1 + (size_t)sSrc[r1] * D + col);
                const float2 p2b = *reinterpret_cast<const float2*>(g_P2 + (size_t)sDst[r1] * D + col);
                v0 += p1a.x + p2a.x; v1 += p1a.y + p2a.y;
                v2 += p1b.x + p2b.x; v3 += p1b.y + p2b.y;
            }
            v0 = elu1(v0); v1 = elu1(v1); v2 = elu1(v2); v3 = elu1(v3);
            uint32_t hi, lo;
            split2t(v0, v1, hi, lo);
            *reinterpret_cast<uint32_t*>(Ah + r0 * TILE_PITCH + col * 2) = hi;
            *reinterpret_cast<uint32_t*>(Al + r0 * TILE_PITCH + col * 2) = lo;
            split2t(v2, v3, hi, lo);
            *reinterpret_cast<uint32_t*>(Ah + r1 * TILE_PITCH + col * 2) = hi;
            *reinterpret_cast<uint32_t*>(Al + r1 * TILE_PITCH + col * 2) = lo;
        }
    }
    CP_WAIT0();       // W2 resident
    __syncthreads();

    // ---- GEMM2 ----
#pragma unroll
    for (int i = 0; i < 2; i++)
#pragma unroll
        for (int j = 0; j < 4; j++) {
            int col = wn * 32 + j * 8 + 2 * tig;
            acc[i][j][0] = sB2[col]; acc[i][j][1] = sB2[col + 1];
            acc[i][j][2] = sB2[col]; acc[i][j][3] = sB2[col + 1];
        }
    warp_gemm3(uAh, uAl, smem_u32(W2h), smem_u32(W2l), lane, wm, wn, acc);

    // ---- epilogue2: h2 = elu(acc) -> gmem + smem scratch (stats) ----
    // scratch overlays W1h/W1l (GEMM2 reads only W2h/W2l/A tiles -> safe)
    float* scratch = reinterpret_cast<float*>(W1h);  // 128 x 132 fp32 = 67584 B
#pragma unroll
    for (int i = 0; i < 2; i++) {
        int r0 = wm * 32 + i * 16 + g;
        int r1 = r0 + 8;
        int gr0 = row0 + r0, gr1 = row0 + r1;
        bool va = gr0 < nrows, vb = gr1 < nrows;
#pragma unroll
        for (int j = 0; j < 4; j++) {
            int col = wn * 32 + j * 8 + 2 * tig;
            float v0 = va ? elu1(acc[i][j][0]) : 0.f;
            float v1 = va ? elu1(acc[i][j][1]) : 0.f;
            float v2 = vb ? elu1(acc[i][j][2]) : 0.f;
            float v3 = vb ? elu1(acc[i][j][3]) : 0.f;
            *reinterpret_cast<float2*>(scratch + r0 * 132 + col) = make_float2(v0, v1);
            *reinterpret_cast<float2*>(scratch + r1 * 132 + col) = make_float2(v2, v3);
            if (va) *reinterpret_cast<float2*>(out + (size_t)gr0 * D + col) = make_float2(v0, v1);
            if (vb) *reinterpret_cast<float2*>(out + (size_t)gr1 * D + col) = make_float2(v2, v3);
        }
    }
    __syncthreads();

    // 512 threads: col = tid&127, row-block (tid>>7)*32
    {
        int col = tid & 127;
        int rb = (tid >> 7) * 32;
        float s = 0.f, q = 0.f;
#pragma unroll 4
        for (int r = rb; r < rb + 32; r++) {
            float vv = scratch[r * 132 + col];
            s += vv; q += vv * vv;
        }
        atomicAdd(&g_stats[stage * 256 + col], s);
        atomicAdd(&g_stats[stage * 256 + 128 + col], q);
    }
}

// ---------------- SIMT path for small node stages ----------------
__device__ __forceinline__ float2 ffma2(float2 d, float2 a, float2 b) {
    asm("fma.rn.f32x2 %0, %1, %2, %0;"
        : "+l"(reinterpret_cast<unsigned long long&>(d))
        : "l"(reinterpret_cast<unsigned long long&>(a)),
          "l"(reinterpret_cast<unsigned long long&>(b)));
    return d;
}

__device__ __forceinline__ void gemm_tile(const float* __restrict__ Xs,
                                          const float* __restrict__ Ws,
                                          float2 acc[8][4], int tx, int ty) {
#pragma unroll 2
    for (int k = 0; k < 128; k++) {
        float xv[8];
        float2 ww[4];
#pragma unroll
        for (int j = 0; j < 8; j++) xv[j] = Xs[(ty + 16 * j) * PADX + k];
#pragma unroll
        for (int p = 0; p < 4; p++) {
            float w0 = Ws[k * 128 + tx + 32 * p];
            float w1 = Ws[k * 128 + tx + 32 * p + 16];
            ww[p] = make_float2(w0, w1);
        }
#pragma unroll
        for (int j = 0; j < 8; j++) {
            float2 xx = make_float2(xv[j], xv[j]);
#pragma unroll
            for (int p = 0; p < 4; p++) acc[j][p] = ffma2(acc[j][p], xx, ww[p]);
        }
    }
}

// mode 0: raw  mode 1: BN(prev stage) folded (in-kernel coeffs)  mode 2: /deg
__global__ void __launch_bounds__(256, 1)
mlp_kernel(const float* __restrict__ X,
           const float* __restrict__ W1, const float* __restrict__ B1,
           const float* __restrict__ W2, const float* __restrict__ B2,
           float* __restrict__ out, int nrows, int mode, int stage,
           const float* __restrict__ gprev, const float* __restrict__ btprev,
           float cntprev, const float* __restrict__ degp)
{
    extern __shared__ float smemf[];
    float* Xs = smemf;
    float* Ws = smemf + 128 * PADX;
    __shared__ float sB[128];
    __shared__ float sPA[128], sPC[128], sDeg[128];

    const int tid = threadIdx.x;
    const int tx = tid & 15, ty = tid >> 4;
    const int row0 = blockIdx.x * 128;

    if (tid < 128) {
        sB[tid] = B1[tid];
        if (mode == 1) {
            float A, C;
            bn_coeff(stage - 1, cntprev, gprev, btprev, tid, A, C);
            sPA[tid] = A; sPC[tid] = C;
        }
        if (mode == 2) {
            int r = row0 + tid;
            sDeg[tid] = (r < nrows) ? (1.f / fmaxf(degp[r], 1.f)) : 0.f;
        }
    }
    __syncthreads();

#pragma unroll
    for (int t = 0; t < 16; t++) {
        int idx = tid + t * 256;
        int r = idx >> 5;
        int c4 = (idx & 31) << 2;
        int gr = row0 + r;
        float4 v = make_float4(0.f, 0.f, 0.f, 0.f);
        if (gr < nrows) {
            v = *reinterpret_cast<const float4*>(X + (size_t)gr * D + c4);
            if (mode == 1) {
                v.x = v.x * sPA[c4] + sPC[c4];
                v.y = v.y * sPA[c4 + 1] + sPC[c4 + 1];
                v.z = v.z * sPA[c4 + 2] + sPC[c4 + 2];
                v.w = v.w * sPA[c4 + 3] + sPC[c4 + 3];
            } else if (mode == 2) {
                float s = sDeg[r];
                v.x *= s; v.y *= s; v.z *= s; v.w *= s;
            }
        }
        *reinterpret_cast<float4*>(Xs + r * PADX + c4) = v;
        reinterpret_cast<float4*>(Ws)[idx] = reinterpret_cast<const float4*>(W1)[idx];
    }
    __syncthreads();

    float2 acc[8][4];
#pragma unroll
    for (int j = 0; j < 8; j++)
#pragma unroll
        for (int p = 0; p < 4; p++)
            acc[j][p] = make_float2(sB[tx + 32 * p], sB[tx + 32 * p + 16]);

    gemm_tile(Xs, Ws, acc, tx, ty);
#pragma unroll
    for (int j = 0; j < 8; j++)
#pragma unroll
        for (int p = 0; p < 4; p++) {
            acc[j][p].x = elu1(acc[j][p].x);
            acc[j][p].y = elu1(acc[j][p].y);
        }
    __syncthreads();

#pragma unroll
    for (int j = 0; j < 8; j++) {
        int r = ty + 16 * j;
#pragma unroll
        for (int p = 0; p < 4; p++) {
            Xs[r * PADX + tx + 32 * p]      = acc[j][p].x;
            Xs[r * PADX + tx + 32 * p + 16] = acc[j][p].y;
        }
    }
#pragma unroll
    for (int t = 0; t < 16; t++) {
        int idx = tid + t * 256;
        reinterpret_cast<float4*>(Ws)[idx] = reinterpret_cast<const float4*>(W2)[idx];
    }
    if (tid < 128) sB[tid] = B2[tid];
    __syncthreads();

#pragma unroll
    for (int j = 0; j < 8; j++)
#pragma unroll
        for (int p = 0; p < 4; p++)
            acc[j][p] = make_float2(sB[tx + 32 * p], sB[tx + 32 * p + 16]);

    gemm_tile(Xs, Ws, acc, tx, ty);
#pragma unroll
    for (int j = 0; j < 8; j++)
#pragma unroll
        for (int p = 0; p < 4; p++) {
            acc[j][p].x = elu1(acc[j][p].x);
            acc[j][p].y = elu1(acc[j][p].y);
        }
    __syncthreads();

#pragma unroll
    for (int j = 0; j < 8; j++) {
        int r = ty + 16 * j;
        int gr = row0 + r;
        bool valid = gr < nrows;
#pragma unroll
        for (int p = 0; p < 4; p++) {
            int c0 = tx + 32 * p, c1 = c0 + 16;
            float vx = valid ? acc[j][p].x : 0.f;
            float vy = valid ? acc[j][p].y : 0.f;
            Xs[r * PADX + c0] = vx;
            Xs[r * PADX + c1] = vy;
            if (valid) {
                out[(size_t)gr * D + c0] = vx;
                out[(size_t)gr * D + c1] = vy;
            }
        }
    }
    __syncthreads();

    if (tid < 128) {
        float s = 0.f, q = 0.f;
#pragma unroll 4
        for (int r = 0; r < 128; r++) {
            float vv = Xs[r * PADX + tid];
            s += vv; q += vv * vv;
        }
        atomicAdd(&g_stats[stage * 256 + tid], s);
        atomicAdd(&g_stats[stage * 256 + 128 + tid], q);
    }
}

// h_e = BN0(t1)+BN1(u); scatter-sum + degree (BN coeffs computed in-kernel)
__global__ void __launch_bounds__(256)
scatter_kernel(const int* __restrict__ dst, int nedges,
               const float* __restrict__ gs, const float* __restrict__ bts)
{
    __shared__ float sA0[128], sC0[128], sA1[128], sC1[128];
    if (threadIdx.x < 128) {
        int j = threadIdx.x;
        float cnt = (float)nedges;
        float A, C;
        bn_coeff(0, cnt, gs, bts, j, A, C);
        sA0[j] = A; sC0[j] = C;
        bn_coeff(1, cnt, gs + 128, bts + 128, j, A, C);
        sA1[j] = A; sC1[j] = C;
    }
    __syncthreads();

    int lane = threadIdx.x & 31;
    int warp = (blockIdx.x * 256 + threadIdx.x) >> 5;
    int nw = (gridDim.x * 256) >> 5;
    float4 A0 = reinterpret_cast<const float4*>(sA0)[lane];
    float4 C0 = reinterpret_cast<const float4*>(sC0)[lane];
    float4 A1 = reinterpret_cast<const float4*>(sA1)[lane];
    float4 C1 = reinterpret_cast<const float4*>(sC1)[lane];
    for (int e = warp; e < nedges; e += nw) {
        int d = __ldg(dst + e);
        float4 t = reinterpret_cast<const float4*>(g_t1 + (size_t)e * D)[lane];
        float4 u = reinterpret_cast<const float4*>(g_u + (size_t)e * D)[lane];
        float4 h;
        h.x = (t.x * A0.x + C0.x) + (u.x * A1.x + C1.x);
        h.y = (t.y * A0.y + C0.y) + (u.y * A1.y + C1.y);
        h.z = (t.z * A0.z + C0.z) + (u.z * A1.z + C1.z);
        h.w = (t.w * A0.w + C0.w) + (u.w * A1.w + C1.w);
        float* base = g_agg + (size_t)d * D + lane * 4;
        asm volatile("red.global.add.v4.f32 [%0], {%1, %2, %3, %4};"
                     :: "l"(base), "f"(h.x), "f"(h.y), "f"(h.z), "f"(h.w)
                     : "memory");
        if (lane == 0) atomicAdd(&g_deg[d], 1.f);
    }
}

// h_n = BN3(w)+BN2(v); P1/P2 partial products (BN coeffs in-kernel)
__global__ void __launch_bounds__(256, 1)
node_final_kernel(const float* __restrict__ eW1, int nrows,
                  const float* __restrict__ gs, const float* __restrict__ bts)
{
    extern __shared__ float smemf[];
    float* Hs = smemf;
    float* Ws = smemf + 128 * PADX;
    __shared__ float sA2[128], sC2[128], sA3[128], sC3[128];
    const int tid = threadIdx.x;
    const int tx = tid & 15, ty = tid >> 4;
    const int row0 = blockIdx.x * 128;

    if (tid < 128) {
        float cnt = (float)nrows;
        float A, C;
        bn_coeff(2, cnt, gs + 256, bts + 256, tid, A, C);
        sA2[tid] = A; sC2[tid] = C;
        bn_coeff(3, cnt, gs + 384, bts + 384, tid, A, C);
        sA3[tid] = A; sC3[tid] = C;
    }
    __syncthreads();

#pragma unroll
    for (int t = 0; t < 16; t++) {
        int idx = tid + t * 256;
        int r = idx >> 5;
        int c4 = (idx & 31) << 2;
        int gr = row0 + r;
        float4 h = make_float4(0.f, 0.f, 0.f, 0.f);
        if (gr < nrows) {
            float4 v = *reinterpret_cast<const float4*>(g_v + (size_t)gr * D + c4);
            float4 w = *reinterpret_cast<const float4*>(g_w + (size_t)gr * D + c4);
            float4 A2 = reinterpret_cast<const float4*>(sA2)[c4 >> 2];
            float4 C2 = reinterpret_cast<const float4*>(sC2)[c4 >> 2];
            float4 A3 = reinterpret_cast<const float4*>(sA3)[c4 >> 2];
            float4 C3 = reinterpret_cast<const float4*>(sC3)[c4 >> 2];
            h.x = (w.x * A3.x + C3.x) + (v.x * A2.x + C2.x);
            h.y = (w.y * A3.y + C3.y) + (v.y * A2.y + C2.y);
            h.z = (w.z * A3.z + C3.z) + (v.z * A2.z + C2.z);
            h.w = (w.w * A3.w + C3.w) + (v.w * A2.w + C2.w);
        }
        *reinterpret_cast<float4*>(Hs + r * PADX + c4) = h;
        reinterpret_cast<float4*>(Ws)[idx] =
            reinterpret_cast<const float4*>(eW1 + 128 * 128)[idx];
    }
    __syncthreads();

    float2 acc[8][4];
#pragma unroll
    for (int j = 0; j < 8; j++)
#pragma unroll
        for (int p = 0; p < 4; p++) acc[j][p] = make_float2(0.f, 0.f);
    gemm_tile(Hs, Ws, acc, tx, ty);
    __syncthreads();

#pragma unroll
    for (int j = 0; j < 8; j++) {
        int gr = row0 + ty + 16 * j;
        if (gr < nrows)
#pragma unroll
            for (int p = 0; p < 4; p++) {
                g_P1[(size_t)gr * D + tx + 32 * p]      = acc[j][p].x;
                g_P1[(size_t)gr * D + tx + 32 * p + 16] = acc[j][p].y;
            }
    }
#pragma unroll
    for (int t = 0; t < 16; t++) {
        int idx = tid + t * 256;
        reinterpret_cast<float4*>(Ws)[idx] =
            reinterpret_cast<const float4*>(eW1 + 256 * 128)[idx];
    }
    __syncthreads();

#pragma unroll
    for (int j = 0; j < 8; j++)
#pragma unroll
        for (int p = 0; p < 4; p++) acc[j][p] = make_float2(0.f, 0.f);
    gemm_tile(Hs, Ws, acc, tx, ty);

#pragma unroll
    for (int j = 0; j < 8; j++) {
        int gr = row0 + ty + 16 * j;
        if (gr < nrows)
#pragma unroll
            for (int p = 0; p < 4; p++) {
                g_P2[(size_t)gr * D + tx + 32 * p]      = acc[j][p].x;
                g_P2[(size_t)gr * D + tx + 32 * p + 16] = acc[j][p].y;
            }
    }
}

// final in-place BN on output (stage-4 coeffs computed per block)
__global__ void norm_out_kernel(float* __restrict__ out, int n4, float cnt,
                                const float* __restrict__ eg,
                                const float* __restrict__ ebt)
{
    __shared__ float sA[128], sC[128];
    if (threadIdx.x < 128) {
        float A, C;
        bn_coeff(4, cnt, eg, ebt, threadIdx.x, A, C);
        sA[threadIdx.x] = A; sC[threadIdx.x] = C;
    }
    __syncthreads();
    int idx = blockIdx.x * blockDim.x + threadIdx.x;
    if (idx >= n4) return;
    int cv = idx & 31;
    float4 A = reinterpret_cast<const float4*>(sA)[cv];
    float4 C = reinterpret_cast<const float4*>(sC)[cv];
    float4 v = reinterpret_cast<float4*>(out)[idx];
    v.x = v.x * A.x + C.x;
    v.y = v.y * A.y + C.y;
    v.z = v.z * A.z + C.z;
    v.w = v.w * A.w + C.w;
    reinterpret_cast<float4*>(out)[idx] = v;
}

// ---------------- host orchestration ----------------
extern "C" void kernel_launch(void* const* d_in, const int* in_sizes, int n_in,
                              void* d_out, int out_size)
{
    if (n_in < 15) return;
    const float* edata = (const float*)d_in[0];
    const int*   src   = (const int*)d_in[1];
    const int*   dst   = (const int*)d_in[2];
    int w = (n_in >= 16) ? 4 : 3;
    const float* W1s = (const float*)d_in[w + 0];
    const float* b1s = (const float*)d_in[w + 1];
    const float* W2s = (const float*)d_in[w + 2];
    const float* b2s = (const float*)d_in[w + 3];
    const float* gs  = (const float*)d_in[w + 4];
    const float* bts = (const float*)d_in[w + 5];
    const float* eW1 = (const float*)d_in[w + 6];
    const float* eb1 = (const float*)d_in[w + 7];
    const float* eW2 = (const float*)d_in[w + 8];
    const float* eb2 = (const float*)d_in[w + 9];
    const float* eg  = (const float*)d_in[w + 10];
    const float* ebt = (const float*)d_in[w + 11];

    int E = in_sizes[0] / D;
    int N = 20000;

    float *p_t1, *p_u, *p_v, *p_w2, *p_agg, *p_deg;
    cudaGetSymbolAddress((void**)&p_t1, g_t1);
    cudaGetSymbolAddress((void**)&p_u, g_u);
    cudaGetSymbolAddress((void**)&p_v, g_v);
    cudaGetSymbolAddress((void**)&p_w2, g_w);
    cudaGetSymbolAddress((void**)&p_agg, g_agg);
    cudaGetSymbolAddress((void**)&p_deg, g_deg);

    cudaFuncSetAttribute(mlp_kernel, cudaFuncAttributeMaxDynamicSharedMemorySize, SMEM_BYTES);
    cudaFuncSetAttribute(node_final_kernel, cudaFuncAttributeMaxDynamicSharedMemorySize, SMEM_BYTES);
    cudaFuncSetAttribute(tc_mlp_tpl<false>, cudaFuncAttributeMaxDynamicSharedMemorySize, TC_SMEM);
    cudaFuncSetAttribute(tc_mlp_tpl<true>,  cudaFuncAttributeMaxDynamicSharedMemorySize, TC_SMEM);

    cudaMemsetAsync(p_agg, 0, (size_t)NODE_CAP * D * sizeof(float), 0);
    cudaMemsetAsync(p_deg, 0, NODE_CAP * sizeof(float), 0);

    int egrid = (E + 127) / 128;
    int ngrid = (N + 127) / 128;

    // weight prep (also zeroes g_stats)
    prep_weights<<<(6 * 16384 + 255) / 256, 256>>>(W1s, W2s, eW1, eW2);

    // edge MLP0 (tensor cores)
    tc_mlp_tpl<false><<<egrid, 512, TC_SMEM>>>(edata, 0, 1, b1s, b2s,
                                               p_t1, E, 0, 0, nullptr, nullptr, 0.f,
                                               nullptr, nullptr);
    // edge MLP1 (input = BN0(t1), coeffs computed in-kernel from g_stats)
    tc_mlp_tpl<false><<<egrid, 512, TC_SMEM>>>(p_t1, 2, 3, b1s + 128, b2s + 128,
                                               p_u, E, 1, 1, gs, bts, (float)E,
                                               nullptr, nullptr);
    // h_e = BN0(t1)+BN1(u); scatter-sum + degree
    scatter_kernel<<<2048, 256>>>(dst, E, gs, bts);
    // node MLP2 (input = agg / max(deg,1)) — SIMT
    mlp_kernel<<<ngrid, 256, SMEM_BYTES>>>(p_agg, W1s + 2 * 16384, b1s + 256,
                                           W2s + 2 * 16384, b2s + 256,
                                           p_v, N, 2, 2, nullptr, nullptr, 0.f, p_deg);
    // node MLP3 (input = BN2(v)) — SIMT
    mlp_kernel<<<ngrid, 256, SMEM_BYTES>>>(p_v, W1s + 3 * 16384, b1s + 384,
                                           W2s + 3 * 16384, b2s + 384,
                                           p_w2, N, 1, 3, gs + 256, bts + 256, (float)N,
                                           nullptr);
    // h_n + per-node partials P1/P2 through eW1 src/dst slices — SIMT
    node_final_kernel<<<ngrid, 256, SMEM_BYTES>>>(eW1, N, gs, bts);
    // final edge MLP (tensor cores, with gathers) -> d_out (pre-BN)
    tc_mlp_tpl<true><<<egrid, 512, TC_SMEM>>>(edata, 4, 5, eb1, eb2,
                                              (float*)d_out, E, 0, 4, nullptr, nullptr, 0.f,
                                              src, dst);
    // final in-place BN (stage-4 coeffs computed per block)
    int n4 = E * (D / 4);
    norm_out_kernel<<<(n4 + 255) / 256, 256>>>((float*)d_out, n4, (float)E, eg, ebt);
}

// round 10
// speedup vs baseline: 1.0415x; 1.0342x over previous
#include <cuda_runtime.h>
#include <cuda_bf16.h>
#include <math.h>
#include <stdint.h>

#define D 128
#define EPS 1e-5f
#define PADX 132
#define NODE_CAP 20096
#define E_MAX 640000

static const int SMEM_BYTES = (128 * PADX + 128 * 128) * 4;  // SIMT kernels
// TC kernel smem: 6 tiles (Ah, Al, W1h, W1l, W2h, W2l), 128 rows x 272 bytes
#define TILE_PITCH 272
#define TILE_BYTES_PAD (128 * TILE_PITCH)  // 34816
static const int TC_SMEM = 6 * TILE_BYTES_PAD;  // 208896

// ---------------- scratch ----------------
__device__ float g_t1[(size_t)E_MAX * D];
__device__ float g_u [(size_t)E_MAX * D];
__device__ float g_v [(size_t)NODE_CAP * D];
__device__ float g_w [(size_t)NODE_CAP * D];
__device__ float g_P1[(size_t)NODE_CAP * D];
__device__ float g_P2[(size_t)NODE_CAP * D];
__device__ float g_agg[(size_t)NODE_CAP * D];
__device__ float g_deg[NODE_CAP];
__device__ float g_stats[5 * 2 * 128];
// prepped weights: 6 matrices x (hi,lo), each [n][k] bf16 128x128 = 32KB
__device__ __align__(256) unsigned char g_wprep[12 * 32768];

// ---------------- helpers ----------------
// fast ELU: exp(x)-1 via ex2.approx (abs err ~2^-22, fine for 1e-3 budget)
__device__ __forceinline__ float elu1(float x) {
    float e;
    asm("ex2.approx.f32 %0, %1;" : "=f"(e) : "f"(x * 1.4426950408889634f));
    return x > 0.f ? x : (e - 1.0f);
}

__device__ __forceinline__ uint32_t smem_u32(const void* p) {
    uint32_t a;
    asm("{ .reg .u64 t; cvta.to.shared.u64 t, %1; cvt.u32.u64 %0, t; }" : "=r"(a) : "l"(p));
    return a;
}

#define CP_ASYNC16(dst, src) \
    asm volatile("cp.async.cg.shared.global [%0], [%1], 16;" :: "r"(dst), "l"(src))
#define CP_COMMIT() asm volatile("cp.async.commit_group;")
#define CP_WAIT1()  asm volatile("cp.async.wait_group 1;")
#define CP_WAIT0()  asm volatile("cp.async.wait_group 0;")

// compute folded BN coeffs for one stage (call with tid<128, then sync)
__device__ __forceinline__ void bn_coeff(int stage, float cnt,
                                         const float* __restrict__ gv,
                                         const float* __restrict__ btv,
                                         int j, float& A, float& C) {
    float s1 = g_stats[stage * 256 + j];
    float s2 = g_stats[stage * 256 + 128 + j];
    float mu = s1 / cnt;
    float var = s2 / cnt - mu * mu;
    A = gv[j] * rsqrtf(var + EPS);
    C = btv[j] - mu * A;
}

// truncation split: hi = a with low 16 bits zeroed (exact bf16), lo = bf16(a - hi)
__device__ __forceinline__ void split2t(float a, float b, uint32_t& hi, uint32_t& lo) {
    uint32_t ai = __float_as_uint(a), bi = __float_as_uint(b);
    hi = __byte_perm(ai, bi, 0x7632);  // {a.hi16 in low, b.hi16 in high}
    float la = a - __uint_as_float(ai & 0xFFFF0000u);
    float lb = b - __uint_as_float(bi & 0xFFFF0000u);
    asm("cvt.rn.bf16x2.f32 %0, %1, %2;" : "=r"(lo) : "f"(lb), "f"(la));
}

// split 8 fp32 -> bf16 hi/lo, 16B stores to padded tiles
__device__ __forceinline__ void split_store8(const float* v, unsigned char* Ah,
                                             unsigned char* Al, uint32_t off) {
    uint32_t hw[4], lw[4];
#pragma unroll
    for (int i = 0; i < 4; i++) split2t(v[2 * i], v[2 * i + 1], hw[i], lw[i]);
    *reinterpret_cast<uint4*>(Ah + off) = make_uint4(hw[0], hw[1], hw[2], hw[3]);
    *reinterpret_cast<uint4*>(Al + off) = make_uint4(lw[0], lw[1], lw[2], lw[3]);
}

__device__ __forceinline__ void ldm4(uint32_t* r, uint32_t a) {
    asm volatile("ldmatrix.sync.aligned.m8n8.x4.shared.b16 {%0,%1,%2,%3}, [%4];"
                 : "=r"(r[0]), "=r"(r[1]), "=r"(r[2]), "=r"(r[3]) : "r"(a));
}

__device__ __forceinline__ void mma16816(float* c, const uint32_t* a, const uint32_t* b) {
    asm volatile(
        "mma.sync.aligned.m16n8k16.row.col.f32.bf16.bf16.f32 "
        "{%0,%1,%2,%3}, {%4,%5,%6,%7}, {%8,%9}, {%0,%1,%2,%3};"
        : "+f"(c[0]), "+f"(c[1]), "+f"(c[2]), "+f"(c[3])
        : "r"(a[0]), "r"(a[1]), "r"(a[2]), "r"(a[3]), "r"(b[0]), "r"(b[1]));
}

// fused 3-split warp GEMM, k-outer, warp tile m32 x n16 (32 warps cover 128x128)
__device__ __forceinline__ void warp_gemm3(uint32_t Ah, uint32_t Al,
                                           uint32_t Wh, uint32_t Wl,
                                           int lane, int wm, int wn,
                                           float acc[2][2][4]) {
    const int arow = lane & 15;
    const int kA = ((lane >> 4) << 3) * 2;               // byte k-offset
    const int brow = ((lane >> 4) << 3) + (lane & 7);
    const int kB = (((lane >> 3) & 1) << 3) * 2;
    const uint32_t aoff0 = (uint32_t)((wm * 32 + arow) * TILE_PITCH) + kA;
    const uint32_t aoff1 = aoff0 + 16 * TILE_PITCH;
    const uint32_t boff = (uint32_t)((wn * 16 + brow) * TILE_PITCH) + kB;

#pragma unroll
    for (int k0 = 0; k0 < 128; k0 += 16) {
        uint32_t ah0[4], ah1[4], al0[4], al1[4], bh[4], bl[4];
        ldm4(ah0, Ah + aoff0 + k0 * 2);
        ldm4(ah1, Ah + aoff1 + k0 * 2);
        ldm4(al0, Al + aoff0 + k0 * 2);
        ldm4(al1, Al + aoff1 + k0 * 2);
        ldm4(bh, Wh + boff + k0 * 2);
        ldm4(bl, Wl + boff + k0 * 2);
#pragma unroll
        for (int j = 0; j < 2; j++) {
            const uint32_t* bhj = &bh[j * 2];
            mma16816(acc[0][j], ah0, bhj);
            mma16816(acc[1][j], ah1, bhj);
        }
#pragma unroll
        for (int j = 0; j < 2; j++) {
            const uint32_t* bhj = &bh[j * 2];
            mma16816(acc[0][j], al0, bhj);
            mma16816(acc[1][j], al1, bhj);
        }
#pragma unroll
        for (int j = 0; j < 2; j++) {
            const uint32_t* blj = &bl[j * 2];
            mma16816(acc[0][j], ah0, blj);
            mma16816(acc[1][j], ah1, blj);
        }
    }
}

// ---------------- weight prep: transpose + bf16 split (+ zero stats) -------
// m: 0:W1s[0] 1:W2s[0] 2:W1s[1] 3:W2s[1] 4:eW1[0:128,:] 5:eW2
__global__ void prep_weights(const float* __restrict__ W1s, const float* __restrict__ W2s,
                             const float* __restrict__ eW1, const float* __restrict__ eW2)
{
    if (blockIdx.x == 0) {
        for (int i = threadIdx.x; i < 5 * 2 * 128; i += 256) g_stats[i] = 0.f;
    }
    int idx = blockIdx.x * 256 + threadIdx.x;
    if (idx >= 6 * 16384) return;
    int m = idx >> 14;
    int e = idx & 16383;
    int n = e >> 7, k = e & 127;
    const float* W;
    switch (m) {
        case 0: W = W1s; break;
        case 1: W = W2s; break;
        case 2: W = W1s + 16384; break;
        case 3: W = W2s + 16384; break;
        case 4: W = eW1; break;
        default: W = eW2; break;
    }
    float v = W[k * 128 + n];
    __nv_bfloat16 h = __float2bfloat16(v);
    __nv_bfloat16 l = __float2bfloat16(v - __bfloat162float(h));
    *reinterpret_cast<__nv_bfloat16*>(g_wprep + (size_t)(2 * m) * 32768 + (size_t)e * 2) = h;
    *reinterpret_cast<__nv_bfloat16*>(g_wprep + (size_t)(2 * m + 1) * 32768 + (size_t)e * 2) = l;
}

// ---------------- tensor-core fused MLP over 128-row tiles, 1024 threads ---
// mode 0: raw X.  mode 1: X*BN(prev_stage) folded (coeffs computed in-kernel).
template <bool GATHER>
__global__ void __launch_bounds__(1024, 1)
tc_mlp_tpl(const float* __restrict__ X, int m1, int m2,
           const float* __restrict__ B1, const float* __restrict__ B2,
           float* __restrict__ out, int nrows, int mode, int stage,
           const float* __restrict__ gprev, const float* __restrict__ btprev,
           float cntprev,
           const int* __restrict__ srcI, const int* __restrict__ dstI)
{
    extern __shared__ unsigned char smem[];
    unsigned char* Ah  = smem;
    unsigned char* Al  = smem + TILE_BYTES_PAD;
    unsigned char* W1h = smem + 2 * TILE_BYTES_PAD;
    unsigned char* W1l = smem + 3 * TILE_BYTES_PAD;
    unsigned char* W2h = smem + 4 * TILE_BYTES_PAD;
    unsigned char* W2l = smem + 5 * TILE_BYTES_PAD;
    __shared__ float sB1[128], sB2[128], sPA[128], sPC[128];
    __shared__ int sSrc[128], sDst[128];

    const int tid = threadIdx.x, wid = tid >> 5, lane = tid & 31;
    const int wm = wid & 3, wn = wid >> 2;       // warp tile: rows 32*wm, cols 16*wn
    const int g = lane >> 2, tig = lane & 3;
    const int row0 = blockIdx.x * 128;

    // ---- async W1 prefetch (group old), W2 prefetch (group young) ----
    {
        const char* g1 = (const char*)(g_wprep + (size_t)(2 * m1) * 32768);
        const char* g2 = (const char*)(g_wprep + (size_t)(2 * m2) * 32768);
#pragma unroll
        for (int t = 0; t < 2; t++) {
            int idx = tid + 1024 * t;
            uint32_t off = (uint32_t)((idx >> 4) * TILE_PITCH + (idx & 15) * 16);
            CP_ASYNC16(smem_u32(W1h + off), g1 + (size_t)idx * 16);
            CP_ASYNC16(smem_u32(W1l + off), g1 + 32768 + (size_t)idx * 16);
        }
        CP_COMMIT();
#pragma unroll
        for (int t = 0; t < 2; t++) {
            int idx = tid + 1024 * t;
            uint32_t off = (uint32_t)((idx >> 4) * TILE_PITCH + (idx & 15) * 16);
            CP_ASYNC16(smem_u32(W2h + off), g2 + (size_t)idx * 16);
            CP_ASYNC16(smem_u32(W2l + off), g2 + 32768 + (size_t)idx * 16);
        }
        CP_COMMIT();
    }

    if (tid < 128) {
        sB1[tid] = B1[tid];
        sB2[tid] = B2[tid];
        if (mode == 1) {
            float A, C;
            bn_coeff(stage - 1, cntprev, gprev, btprev, tid, A, C);
            sPA[tid] = A; sPC[tid] = C;
        }
        if (GATHER) {
            int gr = row0 + tid;
            sSrc[tid] = (gr < nrows) ? srcI[gr] : 0;
            sDst[tid] = (gr < nrows) ? dstI[gr] : 0;
        }
    }
    __syncthreads();  // sPA/sPC visible before A-load uses them

    // ---- coalesced load + split A tile (8-float groups, lane-contiguous) ----
#pragma unroll
    for (int t = 0; t < 2; t++) {
        int q = tid + 1024 * t;       // 2048 groups of 8 floats
        int r = q >> 4;
        int kp = (q & 15) << 3;
        int gr = row0 + r;
        float v[8];
        if (gr < nrows) {
            float4 a = *reinterpret_cast<const float4*>(X + (size_t)gr * D + kp);
            float4 b = *reinterpret_cast<const float4*>(X + (size_t)gr * D + kp + 4);
            v[0] = a.x; v[1] = a.y; v[2] = a.z; v[3] = a.w;
            v[4] = b.x; v[5] = b.y; v[6] = b.z; v[7] = b.w;
            if (mode == 1) {
#pragma unroll
                for (int i = 0; i < 8; i++) v[i] = v[i] * sPA[kp + i] + sPC[kp + i];
            }
        } else {
#pragma unroll
            for (int i = 0; i < 8; i++) v[i] = 0.f;
        }
        split_store8(v, Ah, Al, (uint32_t)(r * TILE_PITCH + kp * 2));
    }
    CP_WAIT1();       // W1 resident
    __syncthreads();

    const uint32_t uAh = smem_u32(Ah), uAl = smem_u32(Al);

    // ---- GEMM1 ----
    float acc[2][2][4];
#pragma unroll
    for (int i = 0; i < 2; i++)
#pragma unroll
        for (int j = 0; j < 2; j++) {
            int col = wn * 16 + j * 8 + 2 * tig;
            acc[i][j][0] = sB1[col]; acc[i][j][1] = sB1[col + 1];
            acc[i][j][2] = sB1[col]; acc[i][j][3] = sB1[col + 1];
        }
    warp_gemm3(uAh, uAl, smem_u32(W1h), smem_u32(W1l), lane, wm, wn, acc);
    __syncthreads();  // all warps done reading Ah/Al before rewrite

    // ---- epilogue1: h1 = elu(acc [+ P1[src]+P2[dst]]); re-split into A ----
#pragma unroll
    for (int i = 0; i < 2; i++) {
        int r0 = wm * 32 + i * 16 + g;
        int r1 = r0 + 8;
#pragma unroll
        for (int j = 0; j < 2; j++) {
            int col = wn * 16 + j * 8 + 2 * tig;
            float v0 = acc[i][j][0], v1 = acc[i][j][1];
            float v2 = acc[i][j][2], v3 = acc[i][j][3];
            if (GATHER) {
                const float2 p1a = *reinterpret_cast<const float2*>(g_P1 + (size_t)sSrc[r0] * D + col);
                const float2 p2a = *reinterpret_cast<const float2*>(g_P2 + (size_t)sDst[r0] * D + col);
                const float2 p1b = *reinterpret_cast<const float2*>(g_P1 + (size_t)sSrc[r1] * D + col);
                const float2 p2b = *reinterpret_cast<const float2*>(g_P2 + (size_t)sDst[r1] * D + col);
                v0 += p1a.x + p2a.x; v1 += p1a.y + p2a.y;
                v2 += p1b.x + p2b.x; v3 += p1b.y + p2b.y;
            }
            v0 = elu1(v0); v1 = elu1(v1); v2 = elu1(v2); v3 = elu1(v3);
            uint32_t hi, lo;
            split2t(v0, v1, hi, lo);
            *reinterpret_cast<uint32_t*>(Ah + r0 * TILE_PITCH + col * 2) = hi;
            *reinterpret_cast<uint32_t*>(Al + r0 * TILE_PITCH + col * 2) = lo;
            split2t(v2, v3, hi, lo);
            *reinterpret_cast<uint32_t*>(Ah + r1 * TILE_PITCH + col * 2) = hi;
            *reinterpret_cast<uint32_t*>(Al + r1 * TILE_PITCH + col * 2) = lo;
        }
    }
    CP_WAIT0();       // W2 resident
    __syncthreads();

    // ---- GEMM2 ----
#pragma unroll
    for (int i = 0; i < 2; i++)
#pragma unroll
        for (int j = 0; j < 2; j++) {
            int col = wn * 16 + j * 8 + 2 * tig;
            acc[i][j][0] = sB2[col]; acc[i][j][1] = sB2[col + 1];
            acc[i][j][2] = sB2[col]; acc[i][j][3] = sB2[col + 1];
        }
    warp_gemm3(uAh, uAl, smem_u32(W2h), smem_u32(W2l), lane, wm, wn, acc);

    // ---- epilogue2: h2 = elu(acc) -> gmem + smem scratch (stats) ----
    // scratch overlays W1h/W1l (GEMM2 reads only W2h/W2l/A tiles -> safe)
    float* scratch = reinterpret_cast<float*>(W1h);  // 128 x 132 fp32 = 67584 B
#pragma unroll
    for (int i = 0; i < 2; i++) {
        int r0 = wm * 32 + i * 16 + g;
        int r1 = r0 + 8;
        int gr0 = row0 + r0, gr1 = row0 + r1;
        bool va = gr0 < nrows, vb = gr1 < nrows;
#pragma unroll
        for (int j = 0; j < 2; j++) {
            int col = wn * 16 + j * 8 + 2 * tig;
            float v0 = va ? elu1(acc[i][j][0]) : 0.f;
            float v1 = va ? elu1(acc[i][j][1]) : 0.f;
            float v2 = vb ? elu1(acc[i][j][2]) : 0.f;
            float v3 = vb ? elu1(acc[i][j][3]) : 0.f;
            *reinterpret_cast<float2*>(scratch + r0 * 132 + col) = make_float2(v0, v1);
            *reinterpret_cast<float2*>(scratch + r1 * 132 + col) = make_float2(v2, v3);
            if (va) *reinterpret_cast<float2*>(out + (size_t)gr0 * D + col) = make_float2(v0, v1);
            if (vb) *reinterpret_cast<float2*>(out + (size_t)gr1 * D + col) = make_float2(v2, v3);
        }
    }
    __syncthreads();

    // 1024 threads: col = tid&127, row-block (tid>>7)*16
    {
        int col = tid & 127;
        int rb = (tid >> 7) * 16;
        float s = 0.f, q = 0.f;
#pragma unroll 4
        for (int r = rb; r < rb + 16; r++) {
            float vv = scratch[r * 132 + col];
            s += vv; q += vv * vv;
        }
        atomicAdd(&g_stats[stage * 256 + col], s);
        atomicAdd(&g_stats[stage * 256 + 128 + col], q);
    }
}

// ---------------- SIMT path for small node stages ----------------
__device__ __forceinline__ float2 ffma2(float2 d, float2 a, float2 b) {
    asm("fma.rn.f32x2 %0, %1, %2, %0;"
        : "+l"(reinterpret_cast<unsigned long long&>(d))
        : "l"(reinterpret_cast<unsigned long long&>(a)),
          "l"(reinterpret_cast<unsigned long long&>(b)));
    return d;
}

__device__ __forceinline__ void gemm_tile(const float* __restrict__ Xs,
                                          const float* __restrict__ Ws,
                                          float2 acc[8][4], int tx, int ty) {
#pragma unroll 2
    for (int k = 0; k < 128; k++) {
        float xv[8];
        float2 ww[4];
#pragma unroll
        for (int j = 0; j < 8; j++) xv[j] = Xs[(ty + 16 * j) * PADX + k];
#pragma unroll
        for (int p = 0; p < 4; p++) {
            float w0 = Ws[k * 128 + tx + 32 * p];
            float w1 = Ws[k * 128 + tx + 32 * p + 16];
            ww[p] = make_float2(w0, w1);
        }
#pragma unroll
        for (int j = 0; j < 8; j++) {
            float2 xx = make_float2(xv[j], xv[j]);
#pragma unroll
            for (int p = 0; p < 4; p++) acc[j][p] = ffma2(acc[j][p], xx, ww[p]);
        }
    }
}

// mode 0: raw  mode 1: BN(prev stage) folded (in-kernel coeffs)  mode 2: /deg
__global__ void __launch_bounds__(256, 1)
mlp_kernel(const float* __restrict__ X,
           const float* __restrict__ W1, const float* __restrict__ B1,
           const float* __restrict__ W2, const float* __restrict__ B2,
           float* __restrict__ out, int nrows, int mode, int stage,
           const float* __restrict__ gprev, const float* __restrict__ btprev,
           float cntprev, const float* __restrict__ degp)
{
    extern __shared__ float smemf[];
    float* Xs = smemf;
    float* Ws = smemf + 128 * PADX;
    __shared__ float sB[128];
    __shared__ float sPA[128], sPC[128], sDeg[128];

    const int tid = threadIdx.x;
    const int tx = tid & 15, ty = tid >> 4;
    const int row0 = blockIdx.x * 128;

    if (tid < 128) {
        sB[tid] = B1[tid];
        if (mode == 1) {
            float A, C;
            bn_coeff(stage - 1, cntprev, gprev, btprev, tid, A, C);
            sPA[tid] = A; sPC[tid] = C;
        }
        if (mode == 2) {
            int r = row0 + tid;
            sDeg[tid] = (r < nrows) ? (1.f / fmaxf(degp[r], 1.f)) : 0.f;
        }
    }
    __syncthreads();

#pragma unroll
    for (int t = 0; t < 16; t++) {
        int idx = tid + t * 256;
        int r = idx >> 5;
        int c4 = (idx & 31) << 2;
        int gr = row0 + r;
        float4 v = make_float4(0.f, 0.f, 0.f, 0.f);
        if (gr < nrows) {
            v = *reinterpret_cast<const float4*>(X + (size_t)gr * D + c4);
            if (mode == 1) {
                v.x = v.x * sPA[c4] + sPC[c4];
                v.y = v.y * sPA[c4 + 1] + sPC[c4 + 1];
                v.z = v.z * sPA[c4 + 2] + sPC[c4 + 2];
                v.w = v.w * sPA[c4 + 3] + sPC[c4 + 3];
            } else if (mode == 2) {
                float s = sDeg[r];
                v.x *= s; v.y *= s; v.z *= s; v.w *= s;
            }
        }
        *reinterpret_cast<float4*>(Xs + r * PADX + c4) = v;
        reinterpret_cast<float4*>(Ws)[idx] = reinterpret_cast<const float4*>(W1)[idx];
    }
    __syncthreads();

    float2 acc[8][4];
#pragma unroll
    for (int j = 0; j < 8; j++)
#pragma unroll
        for (int p = 0; p < 4; p++)
            acc[j][p] = make_float2(sB[tx + 32 * p], sB[tx + 32 * p + 16]);

    gemm_tile(Xs, Ws, acc, tx, ty);
#pragma unroll
    for (int j = 0; j < 8; j++)
#pragma unroll
        for (int p = 0; p < 4; p++) {
            acc[j][p].x = elu1(acc[j][p].x);
            acc[j][p].y = elu1(acc[j][p].y);
        }
    __syncthreads();

#pragma unroll
    for (int j = 0; j < 8; j++) {
        int r = ty + 16 * j;
#pragma unroll
        for (int p = 0; p < 4; p++) {
            Xs[r * PADX + tx + 32 * p]      = acc[j][p].x;
            Xs[r * PADX + tx + 32 * p + 16] = acc[j][p].y;
        }
    }
#pragma unroll
    for (int t = 0; t < 16; t++) {
        int idx = tid + t * 256;
        reinterpret_cast<float4*>(Ws)[idx] = reinterpret_cast<const float4*>(W2)[idx];
    }
    if (tid < 128) sB[tid] = B2[tid];
    __syncthreads();

#pragma unroll
    for (int j = 0; j < 8; j++)
#pragma unroll
        for (int p = 0; p < 4; p++)
            acc[j][p] = make_float2(sB[tx + 32 * p], sB[tx + 32 * p + 16]);

    gemm_tile(Xs, Ws, acc, tx, ty);
#pragma unroll
    for (int j = 0; j < 8; j++)
#pragma unroll
        for (int p = 0; p < 4; p++) {
            acc[j][p].x = elu1(acc[j][p].x);
            acc[j][p].y = elu1(acc[j][p].y);
        }
    __syncthreads();

#pragma unroll
    for (int j = 0; j < 8; j++) {
        int r = ty + 16 * j;
        int gr = row0 + r;
        bool valid = gr < nrows;
#pragma unroll
        for (int p = 0; p < 4; p++) {
            int c0 = tx + 32 * p, c1 = c0 + 16;
            float vx = valid ? acc[j][p].x : 0.f;
            float vy = valid ? acc[j][p].y : 0.f;
            Xs[r * PADX + c0] = vx;
            Xs[r * PADX + c1] = vy;
            if (valid) {
                out[(size_t)gr * D + c0] = vx;
                out[(size_t)gr * D + c1] = vy;
            }
        }
    }
    __syncthreads();

    if (tid < 128) {
        float s = 0.f, q = 0.f;
#pragma unroll 4
        for (int r = 0; r < 128; r++) {
            float vv = Xs[r * PADX + tid];
            s += vv; q += vv * vv;
        }
        atomicAdd(&g_stats[stage * 256 + tid], s);
        atomicAdd(&g_stats[stage * 256 + 128 + tid], q);
    }
}

// h_e = BN0(t1)+BN1(u); scatter-sum + degree (BN coeffs computed in-kernel)
__global__ void __launch_bounds__(256)
scatter_kernel(const int* __restrict__ dst, int nedges,
               const float* __restrict__ gs, const float* __restrict__ bts)
{
    __shared__ float sA0[128], sC0[128], sA1[128], sC1[128];
    if (threadIdx.x < 128) {
        int j = threadIdx.x;
        float cnt = (float)nedges;
        float A, C;
        bn_coeff(0, cnt, gs, bts, j, A, C);
        sA0[j] = A; sC0[j] = C;
        bn_coeff(1, cnt, gs + 128, bts + 128, j, A, C);
        sA1[j] = A; sC1[j] = C;
    }
    __syncthreads();

    int lane = threadIdx.x & 31;
    int warp = (blockIdx.x * 256 + threadIdx.x) >> 5;
    int nw = (gridDim.x * 256) >> 5;
    float4 A0 = reinterpret_cast<const float4*>(sA0)[lane];
    float4 C0 = reinterpret_cast<const float4*>(sC0)[lane];
    float4 A1 = reinterpret_cast<const float4*>(sA1)[lane];
    float4 C1 = reinterpret_cast<const float4*>(sC1)[lane];
    for (int e = warp; e < nedges; e += nw) {
        int d = __ldg(dst + e);
        float4 t = reinterpret_cast<const float4*>(g_t1 + (size_t)e * D)[lane];
        float4 u = reinterpret_cast<const float4*>(g_u + (size_t)e * D)[lane];
        float4 h;
        h.x = (t.x * A0.x + C0.x) + (u.x * A1.x + C1.x);
        h.y = (t.y * A0.y + C0.y) + (u.y * A1.y + C1.y);
        h.z = (t.z * A0.z + C0.z) + (u.z * A1.z + C1.z);
        h.w = (t.w * A0.w + C0.w) + (u.w * A1.w + C1.w);
        float* base = g_agg + (size_t)d * D + lane * 4;
        asm volatile("red.global.add.v4.f32 [%0], {%1, %2, %3, %4};"
                     :: "l"(base), "f"(h.x), "f"(h.y), "f"(h.z), "f"(h.w)
                     : "memory");
        if (lane == 0) atomicAdd(&g_deg[d], 1.f);
    }
}

// h_n = BN3(w)+BN2(v); P1/P2 partial products (BN coeffs in-kernel)
__global__ void __launch_bounds__(256, 1)
node_final_kernel(const float* __restrict__ eW1, int nrows,
                  const float* __restrict__ gs, const float* __restrict__ bts)
{
    extern __shared__ float smemf[];
    float* Hs = smemf;
    float* Ws = smemf + 128 * PADX;
    __shared__ float sA2[128], sC2[128], sA3[128], sC3[128];
    const int tid = threadIdx.x;
    const int tx = tid & 15, ty = tid >> 4;
    const int row0 = blockIdx.x * 128;

    if (tid < 128) {
        float cnt = (float)nrows;
        float A, C;
        bn_coeff(2, cnt, gs + 256, bts + 256, tid, A, C);
        sA2[tid] = A; sC2[tid] = C;
        bn_coeff(3, cnt, gs + 384, bts + 384, tid, A, C);
        sA3[tid] = A; sC3[tid] = C;
    }
    __syncthreads();

#pragma unroll
    for (int t = 0; t < 16; t++) {
        int idx = tid + t * 256;
        int r = idx >> 5;
        int c4 = (idx & 31) << 2;
        int gr = row0 + r;
        float4 h = make_float4(0.f, 0.f, 0.f, 0.f);
        if (gr < nrows) {
            float4 v = *reinterpret_cast<const float4*>(g_v + (size_t)gr * D + c4);
            float4 w = *reinterpret_cast<const float4*>(g_w + (size_t)gr * D + c4);
            float4 A2 = reinterpret_cast<const float4*>(sA2)[c4 >> 2];
            float4 C2 = reinterpret_cast<const float4*>(sC2)[c4 >> 2];
            float4 A3 = reinterpret_cast<const float4*>(sA3)[c4 >> 2];
            float4 C3 = reinterpret_cast<const float4*>(sC3)[c4 >> 2];
            h.x = (w.x * A3.x + C3.x) + (v.x * A2.x + C2.x);
            h.y = (w.y * A3.y + C3.y) + (v.y * A2.y + C2.y);
            h.z = (w.z * A3.z + C3.z) + (v.z * A2.z + C2.z);
            h.w = (w.w * A3.w + C3.w) + (v.w * A2.w + C2.w);
        }
        *reinterpret_cast<float4*>(Hs + r * PADX + c4) = h;
        reinterpret_cast<float4*>(Ws)[idx] =
            reinterpret_cast<const float4*>(eW1 + 128 * 128)[idx];
    }
    __syncthreads();

    float2 acc[8][4];
#pragma unroll
    for (int j = 0; j < 8; j++)
#pragma unroll
        for (int p = 0; p < 4; p++) acc[j][p] = make_float2(0.f, 0.f);
    gemm_tile(Hs, Ws, acc, tx, ty);
    __syncthreads();

#pragma unroll
    for (int j = 0; j < 8; j++) {
        int gr = row0 + ty + 16 * j;
        if (gr < nrows)
#pragma unroll
            for (int p = 0; p < 4; p++) {
                g_P1[(size_t)gr * D + tx + 32 * p]      = acc[j][p].x;
                g_P1[(size_t)gr * D + tx + 32 * p + 16] = acc[j][p].y;
            }
    }
#pragma unroll
    for (int t = 0; t < 16; t++) {
        int idx = tid + t * 256;
        reinterpret_cast<float4*>(Ws)[idx] =
            reinterpret_cast<const float4*>(eW1 + 256 * 128)[idx];
    }
    __syncthreads();

#pragma unroll
    for (int j = 0; j < 8; j++)
#pragma unroll
        for (int p = 0; p < 4; p++) acc[j][p] = make_float2(0.f, 0.f);
    gemm_tile(Hs, Ws, acc, tx, ty);

#pragma unroll
    for (int j = 0; j < 8; j++) {
        int gr = row0 + ty + 16 * j;
        if (gr < nrows)
#pragma unroll
            for (int p = 0; p < 4; p++) {
                g_P2[(size_t)gr * D + tx + 32 * p]      = acc[j][p].x;
                g_P2[(size_t)gr * D + tx + 32 * p + 16] = acc[j][p].y;
            }
    }
}

// final in-place BN on output (stage-4 coeffs computed per block)
__global__ void norm_out_kernel(float* __restrict__ out, int n4, float cnt,
                                const float* __restrict__ eg,
                                const float* __restrict__ ebt)
{
    __shared__ float sA[128], sC[128];
    if (threadIdx.x < 128) {
        float A, C;
        bn_coeff(4, cnt, eg, ebt, threadIdx.x, A, C);
        sA[threadIdx.x] = A; sC[threadIdx.x] = C;
    }
    __syncthreads();
    int idx = blockIdx.x * blockDim.x + threadIdx.x;
    if (idx >= n4) return;
    int cv = idx & 31;
    float4 A = reinterpret_cast<const float4*>(sA)[cv];
    float4 C = reinterpret_cast<const float4*>(sC)[cv];
    float4 v = reinterpret_cast<float4*>(out)[idx];
    v.x = v.x * A.x + C.x;
    v.y = v.y * A.y + C.y;
    v.z = v.z * A.z + C.z;
    v.w = v.w * A.w + C.w;
    reinterpret_cast<float4*>(out)[idx] = v;
}

// ---------------- host orchestration ----------------
extern "C" void kernel_launch(void* const* d_in, const int* in_sizes, int n_in,
                              void* d_out, int out_size)
{
    if (n_in < 15) return;
    const float* edata = (const float*)d_in[0];
    const int*   src   = (const int*)d_in[1];
    const int*   dst   = (const int*)d_in[2];
    int w = (n_in >= 16) ? 4 : 3;
    const float* W1s = (const float*)d_in[w + 0];
    const float* b1s = (const float*)d_in[w + 1];
    const float* W2s = (const float*)d_in[w + 2];
    const float* b2s = (const float*)d_in[w + 3];
    const float* gs  = (const float*)d_in[w + 4];
    const float* bts = (const float*)d_in[w + 5];
    const float* eW1 = (const float*)d_in[w + 6];
    const float* eb1 = (const float*)d_in[w + 7];
    const float* eW2 = (const float*)d_in[w + 8];
    const float* eb2 = (const float*)d_in[w + 9];
    const float* eg  = (const float*)d_in[w + 10];
    const float* ebt = (const float*)d_in[w + 11];

    int E = in_sizes[0] / D;
    int N = 20000;

    float *p_t1, *p_u, *p_v, *p_w2, *p_agg, *p_deg;
    cudaGetSymbolAddress((void**)&p_t1, g_t1);
    cudaGetSymbolAddress((void**)&p_u, g_u);
    cudaGetSymbolAddress((void**)&p_v, g_v);
    cudaGetSymbolAddress((void**)&p_w2, g_w);
    cudaGetSymbolAddress((void**)&p_agg, g_agg);
    cudaGetSymbolAddress((void**)&p_deg, g_deg);

    cudaFuncSetAttribute(mlp_kernel, cudaFuncAttributeMaxDynamicSharedMemorySize, SMEM_BYTES);
    cudaFuncSetAttribute(node_final_kernel, cudaFuncAttributeMaxDynamicSharedMemorySize, SMEM_BYTES);
    cudaFuncSetAttribute(tc_mlp_tpl<false>, cudaFuncAttributeMaxDynamicSharedMemorySize, TC_SMEM);
    cudaFuncSetAttribute(tc_mlp_tpl<true>,  cudaFuncAttributeMaxDynamicSharedMemorySize, TC_SMEM);

    cudaMemsetAsync(p_agg, 0, (size_t)NODE_CAP * D * sizeof(float), 0);
    cudaMemsetAsync(p_deg, 0, NODE_CAP * sizeof(float), 0);

    int egrid = (E + 127) / 128;
    int ngrid = (N + 127) / 128;

    // weight prep (also zeroes g_stats)
    prep_weights<<<(6 * 16384 + 255) / 256, 256>>>(W1s, W2s, eW1, eW2);

    // edge MLP0 (tensor cores)
    tc_mlp_tpl<false><<<egrid, 1024, TC_SMEM>>>(edata, 0, 1, b1s, b2s,
                                                p_t1, E, 0, 0, nullptr, nullptr, 0.f,
                                                nullptr, nullptr);
    // edge MLP1 (input = BN0(t1), coeffs computed in-kernel from g_stats)
    tc_mlp_tpl<false><<<egrid, 1024, TC_SMEM>>>(p_t1, 2, 3, b1s + 128, b2s + 128,
                                                p_u, E, 1, 1, gs, bts, (float)E,
                                                nullptr, nullptr);
    // h_e = BN0(t1)+BN1(u); scatter-sum + degree
    scatter_kernel<<<2048, 256>>>(dst, E, gs, bts);
    // node MLP2 (input = agg / max(deg,1)) — SIMT
    mlp_kernel<<<ngrid, 256, SMEM_BYTES>>>(p_agg, W1s + 2 * 16384, b1s + 256,
                                           W2s + 2 * 16384, b2s + 256,
                                           p_v, N, 2, 2, nullptr, nullptr, 0.f, p_deg);
    // node MLP3 (input = BN2(v)) — SIMT
    mlp_kernel<<<ngrid, 256, SMEM_BYTES>>>(p_v, W1s + 3 * 16384, b1s + 384,
                                           W2s + 3 * 16384, b2s + 384,
                                           p_w2, N, 1, 3, gs + 256, bts + 256, (float)N,
                                           nullptr);
    // h_n + per-node partials P1/P2 through eW1 src/dst slices — SIMT
    node_final_kernel<<<ngrid, 256, SMEM_BYTES>>>(eW1, N, gs, bts);
    // final edge MLP (tensor cores, with gathers) -> d_out (pre-BN)
    tc_mlp_tpl<true><<<egrid, 1024, TC_SMEM>>>(edata, 4, 5, eb1, eb2,
                                               (float*)d_out, E, 0, 4, nullptr, nullptr, 0.f,
                                               src, dst);
    // final in-place BN (stage-4 coeffs computed per block)
    int n4 = E * (D / 4);
    norm_out_kernel<<<(n4 + 255) / 256, 256>>>((float*)d_out, n4, (float)E, eg, ebt);
}

// round 11
// speedup vs baseline: 1.0836x; 1.0404x over previous
#include <cuda_runtime.h>
#include <cuda_bf16.h>
#include <math.h>
#include <stdint.h>

#define D 128
#define EPS 1e-5f
#define PADX 132
#define NODE_CAP 20096
#define E_MAX 640000

static const int SMEM_BYTES = (128 * PADX + 128 * 128) * 4;  // SIMT kernels
// TC kernel smem: 6 tiles (Ah, Al, W1h, W1l, W2h, W2l), 128 rows x 272 bytes
#define TILE_PITCH 272
#define TILE_BYTES_PAD (128 * TILE_PITCH)  // 34816
static const int TC_SMEM = 6 * TILE_BYTES_PAD;  // 208896

// ---------------- scratch ----------------
__device__ float g_t1[(size_t)E_MAX * D];
__device__ float g_v [(size_t)NODE_CAP * D];
__device__ float g_w [(size_t)NODE_CAP * D];
__device__ float g_P1[(size_t)NODE_CAP * D];
__device__ float g_P2[(size_t)NODE_CAP * D];
__device__ float g_aggT[(size_t)NODE_CAP * D];
__device__ float g_aggU[(size_t)NODE_CAP * D];
__device__ float g_deg[NODE_CAP];
__device__ float g_stats[5 * 2 * 128];
// prepped weights: 6 matrices x (hi,lo), each [n][k] bf16 128x128 = 32KB
__device__ __align__(256) unsigned char g_wprep[12 * 32768];

// ---------------- helpers ----------------
// fast ELU: exp(x)-1 via ex2.approx (abs err ~2^-22, fine for 1e-3 budget)
__device__ __forceinline__ float elu1(float x) {
    float e;
    asm("ex2.approx.f32 %0, %1;" : "=f"(e) : "f"(x * 1.4426950408889634f));
    return x > 0.f ? x : (e - 1.0f);
}

__device__ __forceinline__ uint32_t smem_u32(const void* p) {
    uint32_t a;
    asm("{ .reg .u64 t; cvta.to.shared.u64 t, %1; cvt.u32.u64 %0, t; }" : "=r"(a) : "l"(p));
    return a;
}

#define CP_ASYNC16(dst, src) \
    asm volatile("cp.async.cg.shared.global [%0], [%1], 16;" :: "r"(dst), "l"(src))
#define CP_COMMIT() asm volatile("cp.async.commit_group;")
#define CP_WAIT1()  asm volatile("cp.async.wait_group 1;")
#define CP_WAIT0()  asm volatile("cp.async.wait_group 0;")

#define RED2(addr, a, b) \
    asm volatile("red.global.add.v2.f32 [%0], {%1, %2};" \
                 :: "l"(addr), "f"(a), "f"(b) : "memory")

// compute folded BN coeffs for one stage (call with tid<128, then sync)
__device__ __forceinline__ void bn_coeff(int stage, float cnt,
                                         const float* __restrict__ gv,
                                         const float* __restrict__ btv,
                                         int j, float& A, float& C) {
    float s1 = g_stats[stage * 256 + j];
    float s2 = g_stats[stage * 256 + 128 + j];
    float mu = s1 / cnt;
    float var = s2 / cnt - mu * mu;
    A = gv[j] * rsqrtf(var + EPS);
    C = btv[j] - mu * A;
}

// truncation split: hi = a with low 16 bits zeroed (exact bf16), lo = bf16(a - hi)
__device__ __forceinline__ void split2t(float a, float b, uint32_t& hi, uint32_t& lo) {
    uint32_t ai = __float_as_uint(a), bi = __float_as_uint(b);
    hi = __byte_perm(ai, bi, 0x7632);  // {a.hi16 in low, b.hi16 in high}
    float la = a - __uint_as_float(ai & 0xFFFF0000u);
    float lb = b - __uint_as_float(bi & 0xFFFF0000u);
    asm("cvt.rn.bf16x2.f32 %0, %1, %2;" : "=r"(lo) : "f"(lb), "f"(la));
}

// split 8 fp32 -> bf16 hi/lo, 16B stores to padded tiles
__device__ __forceinline__ void split_store8(const float* v, unsigned char* Ah,
                                             unsigned char* Al, uint32_t off) {
    uint32_t hw[4], lw[4];
#pragma unroll
    for (int i = 0; i < 4; i++) split2t(v[2 * i], v[2 * i + 1], hw[i], lw[i]);
    *reinterpret_cast<uint4*>(Ah + off) = make_uint4(hw[0], hw[1], hw[2], hw[3]);
    *reinterpret_cast<uint4*>(Al + off) = make_uint4(lw[0], lw[1], lw[2], lw[3]);
}

__device__ __forceinline__ void ldm4(uint32_t* r, uint32_t a) {
    asm volatile("ldmatrix.sync.aligned.m8n8.x4.shared.b16 {%0,%1,%2,%3}, [%4];"
                 : "=r"(r[0]), "=r"(r[1]), "=r"(r[2]), "=r"(r[3]) : "r"(a));
}

__device__ __forceinline__ void mma16816(float* c, const uint32_t* a, const uint32_t* b) {
    asm volatile(
        "mma.sync.aligned.m16n8k16.row.col.f32.bf16.bf16.f32 "
        "{%0,%1,%2,%3}, {%4,%5,%6,%7}, {%8,%9}, {%0,%1,%2,%3};"
        : "+f"(c[0]), "+f"(c[1]), "+f"(c[2]), "+f"(c[3])
        : "r"(a[0]), "r"(a[1]), "r"(a[2]), "r"(a[3]), "r"(b[0]), "r"(b[1]));
}

// fused 3-split warp GEMM, k-outer, warp tile m32 x n16 (32 warps cover 128x128)
__device__ __forceinline__ void warp_gemm3(uint32_t Ah, uint32_t Al,
                                           uint32_t Wh, uint32_t Wl,
                                           int lane, int wm, int wn,
                                           float acc[2][2][4]) {
    const int arow = lane & 15;
    const int kA = ((lane >> 4) << 3) * 2;               // byte k-offset
    const int brow = ((lane >> 4) << 3) + (lane & 7);
    const int kB = (((lane >> 3) & 1) << 3) * 2;
    const uint32_t aoff0 = (uint32_t)((wm * 32 + arow) * TILE_PITCH) + kA;
    const uint32_t aoff1 = aoff0 + 16 * TILE_PITCH;
    const uint32_t boff = (uint32_t)((wn * 16 + brow) * TILE_PITCH) + kB;

#pragma unroll
    for (int k0 = 0; k0 < 128; k0 += 16) {
        uint32_t ah0[4], ah1[4], al0[4], al1[4], bh[4], bl[4];
        ldm4(ah0, Ah + aoff0 + k0 * 2);
        ldm4(ah1, Ah + aoff1 + k0 * 2);
        ldm4(al0, Al + aoff0 + k0 * 2);
        ldm4(al1, Al + aoff1 + k0 * 2);
        ldm4(bh, Wh + boff + k0 * 2);
        ldm4(bl, Wl + boff + k0 * 2);
#pragma unroll
        for (int j = 0; j < 2; j++) {
            const uint32_t* bhj = &bh[j * 2];
            mma16816(acc[0][j], ah0, bhj);
            mma16816(acc[1][j], ah1, bhj);
        }
#pragma unroll
        for (int j = 0; j < 2; j++) {
            const uint32_t* bhj = &bh[j * 2];
            mma16816(acc[0][j], al0, bhj);
            mma16816(acc[1][j], al1, bhj);
        }
#pragma unroll
        for (int j = 0; j < 2; j++) {
            const uint32_t* blj = &bl[j * 2];
            mma16816(acc[0][j], ah0, blj);
            mma16816(acc[1][j], ah1, blj);
        }
    }
}

// ---------------- weight prep: transpose + bf16 split (+ zero stats) -------
// m: 0:W1s[0] 1:W2s[0] 2:W1s[1] 3:W2s[1] 4:eW1[0:128,:] 5:eW2
__global__ void prep_weights(const float* __restrict__ W1s, const float* __restrict__ W2s,
                             const float* __restrict__ eW1, const float* __restrict__ eW2)
{
    if (blockIdx.x == 0) {
        for (int i = threadIdx.x; i < 5 * 2 * 128; i += 256) g_stats[i] = 0.f;
    }
    int idx = blockIdx.x * 256 + threadIdx.x;
    if (idx >= 6 * 16384) return;
    int m = idx >> 14;
    int e = idx & 16383;
    int n = e >> 7, k = e & 127;
    const float* W;
    switch (m) {
        case 0: W = W1s; break;
        case 1: W = W2s; break;
        case 2: W = W1s + 16384; break;
        case 3: W = W2s + 16384; break;
        case 4: W = eW1; break;
        default: W = eW2; break;
    }
    float v = W[k * 128 + n];
    __nv_bfloat16 h = __float2bfloat16(v);
    __nv_bfloat16 l = __float2bfloat16(v - __bfloat162float(h));
    *reinterpret_cast<__nv_bfloat16*>(g_wprep + (size_t)(2 * m) * 32768 + (size_t)e * 2) = h;
    *reinterpret_cast<__nv_bfloat16*>(g_wprep + (size_t)(2 * m + 1) * 32768 + (size_t)e * 2) = l;
}

// ---------------- tensor-core fused MLP over 128-row tiles, 1024 threads ---
// mode 0: raw X.  mode 1: X*BN(prev_stage) folded (coeffs computed in-kernel).
// wmode 0: write out only.  1: write out + red to aggp[dst] + deg.  2: red only.
template <bool GATHER>
__global__ void __launch_bounds__(1024, 1)
tc_mlp_tpl(const float* __restrict__ X, int m1, int m2,
           const float* __restrict__ B1, const float* __restrict__ B2,
           float* __restrict__ out, int nrows, int mode, int stage,
           const float* __restrict__ gprev, const float* __restrict__ btprev,
           float cntprev, int wmode, float* __restrict__ aggp,
           const int* __restrict__ srcI, const int* __restrict__ dstI)
{
    extern __shared__ unsigned char smem[];
    unsigned char* Ah  = smem;
    unsigned char* Al  = smem + TILE_BYTES_PAD;
    unsigned char* W1h = smem + 2 * TILE_BYTES_PAD;
    unsigned char* W1l = smem + 3 * TILE_BYTES_PAD;
    unsigned char* W2h = smem + 4 * TILE_BYTES_PAD;
    unsigned char* W2l = smem + 5 * TILE_BYTES_PAD;
    __shared__ float sB1[128], sB2[128], sPA[128], sPC[128];
    __shared__ int sSrc[128], sDst[128];

    const int tid = threadIdx.x, wid = tid >> 5, lane = tid & 31;
    const int wm = wid & 3, wn = wid >> 2;       // warp tile: rows 32*wm, cols 16*wn
    const int g = lane >> 2, tig = lane & 3;
    const int row0 = blockIdx.x * 128;

    // ---- async W1 prefetch (group old), W2 prefetch (group young) ----
    {
        const char* g1 = (const char*)(g_wprep + (size_t)(2 * m1) * 32768);
        const char* g2 = (const char*)(g_wprep + (size_t)(2 * m2) * 32768);
#pragma unroll
        for (int t = 0; t < 2; t++) {
            int idx = tid + 1024 * t;
            uint32_t off = (uint32_t)((idx >> 4) * TILE_PITCH + (idx & 15) * 16);
            CP_ASYNC16(smem_u32(W1h + off), g1 + (size_t)idx * 16);
            CP_ASYNC16(smem_u32(W1l + off), g1 + 32768 + (size_t)idx * 16);
        }
        CP_COMMIT();
#pragma unroll
        for (int t = 0; t < 2; t++) {
            int idx = tid + 1024 * t;
            uint32_t off = (uint32_t)((idx >> 4) * TILE_PITCH + (idx & 15) * 16);
            CP_ASYNC16(smem_u32(W2h + off), g2 + (size_t)idx * 16);
            CP_ASYNC16(smem_u32(W2l + off), g2 + 32768 + (size_t)idx * 16);
        }
        CP_COMMIT();
    }

    if (tid < 128) {
        sB1[tid] = B1[tid];
        sB2[tid] = B2[tid];
        if (mode == 1) {
            float A, C;
            bn_coeff(stage - 1, cntprev, gprev, btprev, tid, A, C);
            sPA[tid] = A; sPC[tid] = C;
        }
        if (GATHER || wmode >= 1) {
            int gr = row0 + tid;
            sDst[tid] = (gr < nrows) ? dstI[gr] : 0;
            if (GATHER) sSrc[tid] = (gr < nrows) ? srcI[gr] : 0;
        }
    }
    __syncthreads();  // sPA/sPC visible before A-load uses them

    // ---- coalesced load + split A tile (8-float groups, lane-contiguous) ----
#pragma unroll
    for (int t = 0; t < 2; t++) {
        int q = tid + 1024 * t;       // 2048 groups of 8 floats
        int r = q >> 4;
        int kp = (q & 15) << 3;
        int gr = row0 + r;
        float v[8];
        if (gr < nrows) {
            float4 a = *reinterpret_cast<const float4*>(X + (size_t)gr * D + kp);
            float4 b = *reinterpret_cast<const float4*>(X + (size_t)gr * D + kp + 4);
            v[0] = a.x; v[1] = a.y; v[2] = a.z; v[3] = a.w;
            v[4] = b.x; v[5] = b.y; v[6] = b.z; v[7] = b.w;
            if (mode == 1) {
#pragma unroll
                for (int i = 0; i < 8; i++) v[i] = v[i] * sPA[kp + i] + sPC[kp + i];
            }
        } else {
#pragma unroll
            for (int i = 0; i < 8; i++) v[i] = 0.f;
        }
        split_store8(v, Ah, Al, (uint32_t)(r * TILE_PITCH + kp * 2));
    }
    CP_WAIT1();       // W1 resident
    __syncthreads();

    const uint32_t uAh = smem_u32(Ah), uAl = smem_u32(Al);

    // ---- GEMM1 ----
    float acc[2][2][4];
#pragma unroll
    for (int i = 0; i < 2; i++)
#pragma unroll
        for (int j = 0; j < 2; j++) {
            int col = wn * 16 + j * 8 + 2 * tig;
            acc[i][j][0] = sB1[col]; acc[i][j][1] = sB1[col + 1];
            acc[i][j][2] = sB1[col]; acc[i][j][3] = sB1[col + 1];
        }
    warp_gemm3(uAh, uAl, smem_u32(W1h), smem_u32(W1l), lane, wm, wn, acc);
    __syncthreads();  // all warps done reading Ah/Al before rewrite

    // ---- epilogue1: h1 = elu(acc [+ P1[src]+P2[dst]]); re-split into A ----
#pragma unroll
    for (int i = 0; i < 2; i++) {
        int r0 = wm * 32 + i * 16 + g;
        int r1 = r0 + 8;
#pragma unroll
        for (int j = 0; j < 2; j++) {
            int col = wn * 16 + j * 8 + 2 * tig;
            float v0 = acc[i][j][0], v1 = acc[i][j][1];
            float v2 = acc[i][j][2], v3 = acc[i][j][3];
            if (GATHER) {
                const float2 p1a = *reinterpret_cast<const float2*>(g_P1 + (size_t)sSrc[r0] * D + col);
                const float2 p2a = *reinterpret_cast<const float2*>(g_P2 + (size_t)sDst[r0] * D + col);
                const float2 p1b = *reinterpret_cast<const float2*>(g_P1 + (size_t)sSrc[r1] * D + col);
                const float2 p2b = *reinterpret_cast<const float2*>(g_P2 + (size_t)sDst[r1] * D + col);
                v0 += p1a.x + p2a.x; v1 += p1a.y + p2a.y;
                v2 += p1b.x + p2b.x; v3 += p1b.y + p2b.y;
            }
            v0 = elu1(v0); v1 = elu1(v1); v2 = elu1(v2); v3 = elu1(v3);
            uint32_t hi, lo;
            split2t(v0, v1, hi, lo);
            *reinterpret_cast<uint32_t*>(Ah + r0 * TILE_PITCH + col * 2) = hi;
            *reinterpret_cast<uint32_t*>(Al + r0 * TILE_PITCH + col * 2) = lo;
            split2t(v2, v3, hi, lo);
            *reinterpret_cast<uint32_t*>(Ah + r1 * TILE_PITCH + col * 2) = hi;
            *reinterpret_cast<uint32_t*>(Al + r1 * TILE_PITCH + col * 2) = lo;
        }
    }
    CP_WAIT0();       // W2 resident
    __syncthreads();

    // ---- GEMM2 ----
#pragma unroll
    for (int i = 0; i < 2; i++)
#pragma unroll
        for (int j = 0; j < 2; j++) {
            int col = wn * 16 + j * 8 + 2 * tig;
            acc[i][j][0] = sB2[col]; acc[i][j][1] = sB2[col + 1];
            acc[i][j][2] = sB2[col]; acc[i][j][3] = sB2[col + 1];
        }
    warp_gemm3(uAh, uAl, smem_u32(W2h), smem_u32(W2l), lane, wm, wn, acc);

    // ---- epilogue2: h2 = elu(acc) -> gmem / red-scatter + smem stats ----
    float* scratch = reinterpret_cast<float*>(W1h);  // 128 x 132 fp32 (safe)
#pragma unroll
    for (int i = 0; i < 2; i++) {
        int r0 = wm * 32 + i * 16 + g;
        int r1 = r0 + 8;
        int gr0 = row0 + r0, gr1 = row0 + r1;
        bool va = gr0 < nrows, vb = gr1 < nrows;
#pragma unroll
        for (int j = 0; j < 2; j++) {
            int col = wn * 16 + j * 8 + 2 * tig;
            float v0 = va ? elu1(acc[i][j][0]) : 0.f;
            float v1 = va ? elu1(acc[i][j][1]) : 0.f;
            float v2 = vb ? elu1(acc[i][j][2]) : 0.f;
            float v3 = vb ? elu1(acc[i][j][3]) : 0.f;
            *reinterpret_cast<float2*>(scratch + r0 * 132 + col) = make_float2(v0, v1);
            *reinterpret_cast<float2*>(scratch + r1 * 132 + col) = make_float2(v2, v3);
            if (wmode <= 1) {
                if (va) *reinterpret_cast<float2*>(out + (size_t)gr0 * D + col) = make_float2(v0, v1);
                if (vb) *reinterpret_cast<float2*>(out + (size_t)gr1 * D + col) = make_float2(v2, v3);
            }
            if (wmode >= 1) {
                if (va) RED2(aggp + (size_t)sDst[r0] * D + col, v0, v1);
                if (vb) RED2(aggp + (size_t)sDst[r1] * D + col, v2, v3);
            }
        }
    }
    if (wmode == 1 && tid < 128 && (row0 + tid) < nrows) {
        asm volatile("red.global.add.f32 [%0], %1;"
                     :: "l"(g_deg + sDst[tid]), "f"(1.f) : "memory");
    }
    __syncthreads();

    // 1024 threads: col = tid&127, row-block (tid>>7)*16
    {
        int col = tid & 127;
        int rb = (tid >> 7) * 16;
        float s = 0.f, q = 0.f;
#pragma unroll 4
        for (int r = rb; r < rb + 16; r++) {
            float vv = scratch[r * 132 + col];
            s += vv; q += vv * vv;
        }
        atomicAdd(&g_stats[stage * 256 + col], s);
        atomicAdd(&g_stats[stage * 256 + 128 + col], q);
    }
}

// ---------------- SIMT path for small node stages ----------------
__device__ __forceinline__ float2 ffma2(float2 d, float2 a, float2 b) {
    asm("fma.rn.f32x2 %0, %1, %2, %0;"
        : "+l"(reinterpret_cast<unsigned long long&>(d))
        : "l"(reinterpret_cast<unsigned long long&>(a)),
          "l"(reinterpret_cast<unsigned long long&>(b)));
    return d;
}

__device__ __forceinline__ void gemm_tile(const float* __restrict__ Xs,
                                          const float* __restrict__ Ws,
                                          float2 acc[8][4], int tx, int ty) {
#pragma unroll 2
    for (int k = 0; k < 128; k++) {
        float xv[8];
        float2 ww[4];
#pragma unroll
        for (int j = 0; j < 8; j++) xv[j] = Xs[(ty + 16 * j) * PADX + k];
#pragma unroll
        for (int p = 0; p < 4; p++) {
            float w0 = Ws[k * 128 + tx + 32 * p];
            float w1 = Ws[k * 128 + tx + 32 * p + 16];
            ww[p] = make_float2(w0, w1);
        }
#pragma unroll
        for (int j = 0; j < 8; j++) {
            float2 xx = make_float2(xv[j], xv[j]);
#pragma unroll
            for (int p = 0; p < 4; p++) acc[j][p] = ffma2(acc[j][p], xx, ww[p]);
        }
    }
}

// mode 1: BN(prev stage) folded.  mode 2: combine aggT/aggU with BN0+BN1 and /deg
__global__ void __launch_bounds__(256, 1)
mlp_kernel(const float* __restrict__ X, const float* __restrict__ X2,
           const float* __restrict__ W1, const float* __restrict__ B1,
           const float* __restrict__ W2, const float* __restrict__ B2,
           float* __restrict__ out, int nrows, int mode, int stage,
           const float* __restrict__ gprev, const float* __restrict__ btprev,
           float cntprev, const float* __restrict__ degp)
{
    extern __shared__ float smemf[];
    float* Xs = smemf;
    float* Ws = smemf + 128 * PADX;
    __shared__ float sB[128];
    __shared__ float sPA[128], sPC[128], sPA2[128], sPC2[128], sInv[128], sF[128];

    const int tid = threadIdx.x;
    const int tx = tid & 15, ty = tid >> 4;
    const int row0 = blockIdx.x * 128;

    if (tid < 128) {
        sB[tid] = B1[tid];
        if (mode == 1) {
            float A, C;
            bn_coeff(stage - 1, cntprev, gprev, btprev, tid, A, C);
            sPA[tid] = A; sPC[tid] = C;
        }
        if (mode == 2) {
            float A, C;
            bn_coeff(0, cntprev, gprev, btprev, tid, A, C);
            sPA[tid] = A; sPC[tid] = C;
            bn_coeff(1, cntprev, gprev + 128, btprev + 128, tid, A, C);
            sPA2[tid] = A; sPC2[tid] = C;
            int r = row0 + tid;
            float dg = (r < nrows) ? degp[r] : 0.f;
            sInv[tid] = 1.f / fmaxf(dg, 1.f);
            sF[tid] = dg > 0.f ? 1.f : 0.f;
        }
    }
    __syncthreads();

#pragma unroll
    for (int t = 0; t < 16; t++) {
        int idx = tid + t * 256;
        int r = idx >> 5;
        int c4 = (idx & 31) << 2;
        int gr = row0 + r;
        float4 v = make_float4(0.f, 0.f, 0.f, 0.f);
        if (gr < nrows) {
            v = *reinterpret_cast<const float4*>(X + (size_t)gr * D + c4);
            if (mode == 1) {
                v.x = v.x * sPA[c4] + sPC[c4];
                v.y = v.y * sPA[c4 + 1] + sPC[c4 + 1];
                v.z = v.z * sPA[c4 + 2] + sPC[c4 + 2];
                v.w = v.w * sPA[c4 + 3] + sPC[c4 + 3];
            } else if (mode == 2) {
                float4 u = *reinterpret_cast<const float4*>(X2 + (size_t)gr * D + c4);
                float inv = sInv[r], f = sF[r];
                v.x = (sPA[c4] * v.x + sPA2[c4] * u.x) * inv + (sPC[c4] + sPC2[c4]) * f;
                v.y = (sPA[c4+1] * v.y + sPA2[c4+1] * u.y) * inv + (sPC[c4+1] + sPC2[c4+1]) * f;
                v.z = (sPA[c4+2] * v.z + sPA2[c4+2] * u.z) * inv + (sPC[c4+2] + sPC2[c4+2]) * f;
                v.w = (sPA[c4+3] * v.w + sPA2[c4+3] * u.w) * inv + (sPC[c4+3] + sPC2[c4+3]) * f;
            }
        }
        *reinterpret_cast<float4*>(Xs + r * PADX + c4) = v;
        reinterpret_cast<float4*>(Ws)[idx] = reinterpret_cast<const float4*>(W1)[idx];
    }
    __syncthreads();

    float2 acc[8][4];
#pragma unroll
    for (int j = 0; j < 8; j++)
#pragma unroll
        for (int p = 0; p < 4; p++)
            acc[j][p] = make_float2(sB[tx + 32 * p], sB[tx + 32 * p + 16]);

    gemm_tile(Xs, Ws, acc, tx, ty);
#pragma unroll
    for (int j = 0; j < 8; j++)
#pragma unroll
        for (int p = 0; p < 4; p++) {
            acc[j][p].x = elu1(acc[j][p].x);
            acc[j][p].y = elu1(acc[j][p].y);
        }
    __syncthreads();

#pragma unroll
    for (int j = 0; j < 8; j++) {
        int r = ty + 16 * j;
#pragma unroll
        for (int p = 0; p < 4; p++) {
            Xs[r * PADX + tx + 32 * p]      = acc[j][p].x;
            Xs[r * PADX + tx + 32 * p + 16] = acc[j][p].y;
        }
    }
#pragma unroll
    for (int t = 0; t < 16; t++) {
        int idx = tid + t * 256;
        reinterpret_cast<float4*>(Ws)[idx] = reinterpret_cast<const float4*>(W2)[idx];
    }
    if (tid < 128) sB[tid] = B2[tid];
    __syncthreads();

#pragma unroll
    for (int j = 0; j < 8; j++)
#pragma unroll
        for (int p = 0; p < 4; p++)
            acc[j][p] = make_float2(sB[tx + 32 * p], sB[tx + 32 * p + 16]);

    gemm_tile(Xs, Ws, acc, tx, ty);
#pragma unroll
    for (int j = 0; j < 8; j++)
#pragma unroll
        for (int p = 0; p < 4; p++) {
            acc[j][p].x = elu1(acc[j][p].x);
            acc[j][p].y = elu1(acc[j][p].y);
        }
    __syncthreads();

#pragma unroll
    for (int j = 0; j < 8; j++) {
        int r = ty + 16 * j;
        int gr = row0 + r;
        bool valid = gr < nrows;
#pragma unroll
        for (int p = 0; p < 4; p++) {
            int c0 = tx + 32 * p, c1 = c0 + 16;
            float vx = valid ? acc[j][p].x : 0.f;
            float vy = valid ? acc[j][p].y : 0.f;
            Xs[r * PADX + c0] = vx;
            Xs[r * PADX + c1] = vy;
            if (valid) {
                out[(size_t)gr * D + c0] = vx;
                out[(size_t)gr * D + c1] = vy;
            }
        }
    }
    __syncthreads();

    if (tid < 128) {
        float s = 0.f, q = 0.f;
#pragma unroll 4
        for (int r = 0; r < 128; r++) {
            float vv = Xs[r * PADX + tid];
            s += vv; q += vv * vv;
        }
        atomicAdd(&g_stats[stage * 256 + tid], s);
        atomicAdd(&g_stats[stage * 256 + 128 + tid], q);
    }
}

// h_n = BN3(w)+BN2(v); P1/P2 partial products (BN coeffs in-kernel)
__global__ void __launch_bounds__(256, 1)
node_final_kernel(const float* __restrict__ eW1, int nrows,
                  const float* __restrict__ gs, const float* __restrict__ bts)
{
    extern __shared__ float smemf[];
    float* Hs = smemf;
    float* Ws = smemf + 128 * PADX;
    __shared__ float sA2[128], sC2[128], sA3[128], sC3[128];
    const int tid = threadIdx.x;
    const int tx = tid & 15, ty = tid >> 4;
    const int row0 = blockIdx.x * 128;

    if (tid < 128) {
        float cnt = (float)nrows;
        float A, C;
        bn_coeff(2, cnt, gs + 256, bts + 256, tid, A, C);
        sA2[tid] = A; sC2[tid] = C;
        bn_coeff(3, cnt, gs + 384, bts + 384, tid, A, C);
        sA3[tid] = A; sC3[tid] = C;
    }
    __syncthreads();

#pragma unroll
    for (int t = 0; t < 16; t++) {
        int idx = tid + t * 256;
        int r = idx >> 5;
        int c4 = (idx & 31) << 2;
        int gr = row0 + r;
        float4 h = make_float4(0.f, 0.f, 0.f, 0.f);
        if (gr < nrows) {
            float4 v = *reinterpret_cast<const float4*>(g_v + (size_t)gr * D + c4);
            float4 w = *reinterpret_cast<const float4*>(g_w + (size_t)gr * D + c4);
            float4 A2 = reinterpret_cast<const float4*>(sA2)[c4 >> 2];
            float4 C2 = reinterpret_cast<const float4*>(sC2)[c4 >> 2];
            float4 A3 = reinterpret_cast<const float4*>(sA3)[c4 >> 2];
            float4 C3 = reinterpret_cast<const float4*>(sC3)[c4 >> 2];
            h.x = (w.x * A3.x + C3.x) + (v.x * A2.x + C2.x);
            h.y = (w.y * A3.y + C3.y) + (v.y * A2.y + C2.y);
            h.z = (w.z * A3.z + C3.z) + (v.z * A2.z + C2.z);
            h.w = (w.w * A3.w + C3.w) + (v.w * A2.w + C2.w);
        }
        *reinterpret_cast<float4*>(Hs + r * PADX + c4) = h;
        reinterpret_cast<float4*>(Ws)[idx] =
            reinterpret_cast<const float4*>(eW1 + 128 * 128)[idx];
    }
    __syncthreads();

    float2 acc[8][4];
#pragma unroll
    for (int j = 0; j < 8; j++)
#pragma unroll
        for (int p = 0; p < 4; p++) acc[j][p] = make_float2(0.f, 0.f);
    gemm_tile(Hs, Ws, acc, tx, ty);
    __syncthreads();

#pragma unroll
    for (int j = 0; j < 8; j++) {
        int gr = row0 + ty + 16 * j;
        if (gr < nrows)
#pragma unroll
            for (int p = 0; p < 4; p++) {
                g_P1[(size_t)gr * D + tx + 32 * p]      = acc[j][p].x;
                g_P1[(size_t)gr * D + tx + 32 * p + 16] = acc[j][p].y;
            }
    }
#pragma unroll
    for (int t = 0; t < 16; t++) {
        int idx = tid + t * 256;
        reinterpret_cast<float4*>(Ws)[idx] =
            reinterpret_cast<const float4*>(eW1 + 256 * 128)[idx];
    }
    __syncthreads();

#pragma unroll
    for (int j = 0; j < 8; j++)
#pragma unroll
        for (int p = 0; p < 4; p++) acc[j][p] = make_float2(0.f, 0.f);
    gemm_tile(Hs, Ws, acc, tx, ty);

#pragma unroll
    for (int j = 0; j < 8; j++) {
        int gr = row0 + ty + 16 * j;
        if (gr < nrows)
#pragma unroll
            for (int p = 0; p < 4; p++) {
                g_P2[(size_t)gr * D + tx + 32 * p]      = acc[j][p].x;
                g_P2[(size_t)gr * D + tx + 32 * p + 16] = acc[j][p].y;
            }
    }
}

// final in-place BN on output (stage-4 coeffs computed per block)
__global__ void norm_out_kernel(float* __restrict__ out, int n4, float cnt,
                                const float* __restrict__ eg,
                                const float* __restrict__ ebt)
{
    __shared__ float sA[128], sC[128];
    if (threadIdx.x < 128) {
        float A, C;
        bn_coeff(4, cnt, eg, ebt, threadIdx.x, A, C);
        sA[threadIdx.x] = A; sC[threadIdx.x] = C;
    }
    __syncthreads();
    int idx = blockIdx.x * blockDim.x + threadIdx.x;
    if (idx >= n4) return;
    int cv = idx & 31;
    float4 A = reinterpret_cast<const float4*>(sA)[cv];
    float4 C = reinterpret_cast<const float4*>(sC)[cv];
    float4 v = reinterpret_cast<float4*>(out)[idx];
    v.x = v.x * A.x + C.x;
    v.y = v.y * A.y + C.y;
    v.z = v.z * A.z + C.z;
    v.w = v.w * A.w + C.w;
    reinterpret_cast<float4*>(out)[idx] = v;
}

// ---------------- host orchestration ----------------
extern "C" void kernel_launch(void* const* d_in, const int* in_sizes, int n_in,
                              void* d_out, int out_size)
{
    if (n_in < 15) return;
    const float* edata = (const float*)d_in[0];
    const int*   src   = (const int*)d_in[1];
    const int*   dst   = (const int*)d_in[2];
    int w = (n_in >= 16) ? 4 : 3;
    const float* W1s = (const float*)d_in[w + 0];
    const float* b1s = (const float*)d_in[w + 1];
    const float* W2s = (const float*)d_in[w + 2];
    const float* b2s = (const float*)d_in[w + 3];
    const float* gs  = (const float*)d_in[w + 4];
    const float* bts = (const float*)d_in[w + 5];
    const float* eW1 = (const float*)d_in[w + 6];
    const float* eb1 = (const float*)d_in[w + 7];
    const float* eW2 = (const float*)d_in[w + 8];
    const float* eb2 = (const float*)d_in[w + 9];
    const float* eg  = (const float*)d_in[w + 10];
    const float* ebt = (const float*)d_in[w + 11];

    int E = in_sizes[0] / D;
    int N = 20000;

    float *p_t1, *p_v, *p_w2, *p_aggT, *p_aggU, *p_deg;
    cudaGetSymbolAddress((void**)&p_t1, g_t1);
    cudaGetSymbolAddress((void**)&p_v, g_v);
    cudaGetSymbolAddress((void**)&p_w2, g_w);
    cudaGetSymbolAddress((void**)&p_aggT, g_aggT);
    cudaGetSymbolAddress((void**)&p_aggU, g_aggU);
    cudaGetSymbolAddress((void**)&p_deg, g_deg);

    cudaFuncSetAttribute(mlp_kernel, cudaFuncAttributeMaxDynamicSharedMemorySize, SMEM_BYTES);
    cudaFuncSetAttribute(node_final_kernel, cudaFuncAttributeMaxDynamicSharedMemorySize, SMEM_BYTES);
    cudaFuncSetAttribute(tc_mlp_tpl<false>, cudaFuncAttributeMaxDynamicSharedMemorySize, TC_SMEM);
    cudaFuncSetAttribute(tc_mlp_tpl<true>,  cudaFuncAttributeMaxDynamicSharedMemorySize, TC_SMEM);

    cudaMemsetAsync(p_aggT, 0, (size_t)NODE_CAP * D * sizeof(float), 0);
    cudaMemsetAsync(p_aggU, 0, (size_t)NODE_CAP * D * sizeof(float), 0);
    cudaMemsetAsync(p_deg, 0, NODE_CAP * sizeof(float), 0);

    int egrid = (E + 127) / 128;
    int ngrid = (N + 127) / 128;

    // weight prep (also zeroes g_stats)
    prep_weights<<<(6 * 16384 + 255) / 256, 256>>>(W1s, W2s, eW1, eW2);

    // edge MLP0 (tensor cores): write t1 + raw-scatter to aggT + deg
    tc_mlp_tpl<false><<<egrid, 1024, TC_SMEM>>>(edata, 0, 1, b1s, b2s,
                                                p_t1, E, 0, 0, nullptr, nullptr, 0.f,
                                                1, p_aggT, nullptr, dst);
    // edge MLP1 (input = BN0(t1)): NO gmem write; raw-scatter u to aggU
    tc_mlp_tpl<false><<<egrid, 1024, TC_SMEM>>>(p_t1, 2, 3, b1s + 128, b2s + 128,
                                                nullptr, E, 1, 1, gs, bts, (float)E,
                                                2, p_aggU, nullptr, dst);
    // node MLP2: input = (A0*aggT + A1*aggU)/deg + (C0+C1)  — SIMT
    mlp_kernel<<<ngrid, 256, SMEM_BYTES>>>(p_aggT, p_aggU,
                                           W1s + 2 * 16384, b1s + 256,
                                           W2s + 2 * 16384, b2s + 256,
                                           p_v, N, 2, 2, gs, bts, (float)E, p_deg);
    // node MLP3 (input = BN2(v)) — SIMT
    mlp_kernel<<<ngrid, 256, SMEM_BYTES>>>(p_v, nullptr,
                                           W1s + 3 * 16384, b1s + 384,
                                           W2s + 3 * 16384, b2s + 384,
                                           p_w2, N, 1, 3, gs + 256, bts + 256, (float)N,
                                           nullptr);
    // h_n + per-node partials P1/P2 through eW1 src/dst slices — SIMT
    node_final_kernel<<<ngrid, 256, SMEM_BYTES>>>(eW1, N, gs, bts);
    // final edge MLP (tensor cores, with gathers) -> d_out (pre-BN)
    tc_mlp_tpl<true><<<egrid, 1024, TC_SMEM>>>(edata, 4, 5, eb1, eb2,
                                               (float*)d_out, E, 0, 4, nullptr, nullptr, 0.f,
                                               0, nullptr, src, dst);
    // final in-place BN (stage-4 coeffs computed per block)
    int n4 = E * (D / 4);
    norm_out_kernel<<<(n4 + 255) / 256, 256>>>((float*)d_out, n4, (float)E, eg, ebt);
}

// round 12
// speedup vs baseline: 1.1045x; 1.0193x over previous
#include <cuda_runtime.h>
#include <cuda_bf16.h>
#include <math.h>
#include <stdint.h>

#define D 128
#define EPS 1e-5f
#define NODE_CAP 20096
#define E_MAX 640000

// TC kernel smem: 6 tiles (Ah, Al, W1h, W1l, W2h, W2l), 128 rows x 272 bytes
#define TILE_PITCH 272
#define TILE_BYTES_PAD (128 * TILE_PITCH)  // 34816
static const int TC_SMEM = 6 * TILE_BYTES_PAD;  // 208896

// ---------------- scratch ----------------
__device__ float g_t1[(size_t)E_MAX * D];
__device__ float g_v [(size_t)NODE_CAP * D];
__device__ float g_w [(size_t)NODE_CAP * D];
__device__ float g_P1[(size_t)NODE_CAP * D];
__device__ float g_P2[(size_t)NODE_CAP * D];
__device__ float g_aggT[(size_t)NODE_CAP * D];
__device__ float g_aggU[(size_t)NODE_CAP * D];
__device__ float g_deg[NODE_CAP];
__device__ float g_stats[5 * 2 * 128];
// prepped weights: 12 matrices x (hi,lo), each [n][k] bf16 128x128 = 32KB
__device__ __align__(256) unsigned char g_wprep[24 * 32768];

// ---------------- helpers ----------------
__device__ __forceinline__ float elu1(float x) {
    float e;
    asm("ex2.approx.f32 %0, %1;" : "=f"(e) : "f"(x * 1.4426950408889634f));
    return x > 0.f ? x : (e - 1.0f);
}

__device__ __forceinline__ uint32_t smem_u32(const void* p) {
    uint32_t a;
    asm("{ .reg .u64 t; cvta.to.shared.u64 t, %1; cvt.u32.u64 %0, t; }" : "=r"(a) : "l"(p));
    return a;
}

#define CP_ASYNC16(dst, src) \
    asm volatile("cp.async.cg.shared.global [%0], [%1], 16;" :: "r"(dst), "l"(src))
#define CP_COMMIT() asm volatile("cp.async.commit_group;")
#define CP_WAIT1()  asm volatile("cp.async.wait_group 1;")
#define CP_WAIT0()  asm volatile("cp.async.wait_group 0;")

#define RED2(addr, a, b) \
    asm volatile("red.global.add.v2.f32 [%0], {%1, %2};" \
                 :: "l"(addr), "f"(a), "f"(b) : "memory")

// folded BN coeffs for one stage (call with tid<128, then sync)
__device__ __forceinline__ void bn_coeff(int stage, float cnt,
                                         const float* __restrict__ gv,
                                         const float* __restrict__ btv,
                                         int j, float& A, float& C) {
    float s1 = g_stats[stage * 256 + j];
    float s2 = g_stats[stage * 256 + 128 + j];
    float mu = s1 / cnt;
    float var = s2 / cnt - mu * mu;
    A = gv[j] * rsqrtf(var + EPS);
    C = btv[j] - mu * A;
}

// truncation split: hi = a with low 16 bits zeroed, lo = bf16(a - hi)
__device__ __forceinline__ void split2t(float a, float b, uint32_t& hi, uint32_t& lo) {
    uint32_t ai = __float_as_uint(a), bi = __float_as_uint(b);
    hi = __byte_perm(ai, bi, 0x7632);
    float la = a - __uint_as_float(ai & 0xFFFF0000u);
    float lb = b - __uint_as_float(bi & 0xFFFF0000u);
    asm("cvt.rn.bf16x2.f32 %0, %1, %2;" : "=r"(lo) : "f"(lb), "f"(la));
}

__device__ __forceinline__ void split_store8(const float* v, unsigned char* Ah,
                                             unsigned char* Al, uint32_t off) {
    uint32_t hw[4], lw[4];
#pragma unroll
    for (int i = 0; i < 4; i++) split2t(v[2 * i], v[2 * i + 1], hw[i], lw[i]);
    *reinterpret_cast<uint4*>(Ah + off) = make_uint4(hw[0], hw[1], hw[2], hw[3]);
    *reinterpret_cast<uint4*>(Al + off) = make_uint4(lw[0], lw[1], lw[2], lw[3]);
}

__device__ __forceinline__ void ldm4(uint32_t* r, uint32_t a) {
    asm volatile("ldmatrix.sync.aligned.m8n8.x4.shared.b16 {%0,%1,%2,%3}, [%4];"
                 : "=r"(r[0]), "=r"(r[1]), "=r"(r[2]), "=r"(r[3]) : "r"(a));
}

__device__ __forceinline__ void mma16816(float* c, const uint32_t* a, const uint32_t* b) {
    asm volatile(
        "mma.sync.aligned.m16n8k16.row.col.f32.bf16.bf16.f32 "
        "{%0,%1,%2,%3}, {%4,%5,%6,%7}, {%8,%9}, {%0,%1,%2,%3};"
        : "+f"(c[0]), "+f"(c[1]), "+f"(c[2]), "+f"(c[3])
        : "r"(a[0]), "r"(a[1]), "r"(a[2]), "r"(a[3]), "r"(b[0]), "r"(b[1]));
}

// fused 3-split warp GEMM, k-outer, warp tile m32 x n16 (32 warps cover 128x128)
__device__ __forceinline__ void warp_gemm3(uint32_t Ah, uint32_t Al,
                                           uint32_t Wh, uint32_t Wl,
                                           int lane, int wm, int wn,
                                           float acc[2][2][4]) {
    const int arow = lane & 15;
    const int kA = ((lane >> 4) << 3) * 2;
    const int brow = ((lane >> 4) << 3) + (lane & 7);
    const int kB = (((lane >> 3) & 1) << 3) * 2;
    const uint32_t aoff0 = (uint32_t)((wm * 32 + arow) * TILE_PITCH) + kA;
    const uint32_t aoff1 = aoff0 + 16 * TILE_PITCH;
    const uint32_t boff = (uint32_t)((wn * 16 + brow) * TILE_PITCH) + kB;

#pragma unroll
    for (int k0 = 0; k0 < 128; k0 += 16) {
        uint32_t ah0[4], ah1[4], al0[4], al1[4], bh[4], bl[4];
        ldm4(ah0, Ah + aoff0 + k0 * 2);
        ldm4(ah1, Ah + aoff1 + k0 * 2);
        ldm4(al0, Al + aoff0 + k0 * 2);
        ldm4(al1, Al + aoff1 + k0 * 2);
        ldm4(bh, Wh + boff + k0 * 2);
        ldm4(bl, Wl + boff + k0 * 2);
#pragma unroll
        for (int j = 0; j < 2; j++) {
            const uint32_t* bhj = &bh[j * 2];
            mma16816(acc[0][j], ah0, bhj);
            mma16816(acc[1][j], ah1, bhj);
        }
#pragma unroll
        for (int j = 0; j < 2; j++) {
            const uint32_t* bhj = &bh[j * 2];
            mma16816(acc[0][j], al0, bhj);
            mma16816(acc[1][j], al1, bhj);
        }
#pragma unroll
        for (int j = 0; j < 2; j++) {
            const uint32_t* blj = &bl[j * 2];
            mma16816(acc[0][j], ah0, blj);
            mma16816(acc[1][j], ah1, blj);
        }
    }
}

// ---------------- weight prep: transpose + bf16 split (+ zero stats) -------
// m: 0:W1s0 1:W2s0 2:W1s1 3:W2s1 4:eW1a 5:eW2 6:W1s2 7:W2s2 8:W1s3 9:W2s3
//    10:eW1b 11:eW1c
__global__ void prep_weights(const float* __restrict__ W1s, const float* __restrict__ W2s,
                             const float* __restrict__ eW1, const float* __restrict__ eW2)
{
    if (blockIdx.x == 0) {
        for (int i = threadIdx.x; i < 5 * 2 * 128; i += 256) g_stats[i] = 0.f;
    }
    int idx = blockIdx.x * 256 + threadIdx.x;
    if (idx >= 12 * 16384) return;
    int m = idx >> 14;
    int e = idx & 16383;
    int n = e >> 7, k = e & 127;
    const float* W;
    switch (m) {
        case 0:  W = W1s; break;
        case 1:  W = W2s; break;
        case 2:  W = W1s + 16384; break;
        case 3:  W = W2s + 16384; break;
        case 4:  W = eW1; break;
        case 5:  W = eW2; break;
        case 6:  W = W1s + 2 * 16384; break;
        case 7:  W = W2s + 2 * 16384; break;
        case 8:  W = W1s + 3 * 16384; break;
        case 9:  W = W2s + 3 * 16384; break;
        case 10: W = eW1 + 128 * 128; break;
        default: W = eW1 + 256 * 128; break;
    }
    float v = W[k * 128 + n];
    __nv_bfloat16 h = __float2bfloat16(v);
    __nv_bfloat16 l = __float2bfloat16(v - __bfloat162float(h));
    *reinterpret_cast<__nv_bfloat16*>(g_wprep + (size_t)(2 * m) * 32768 + (size_t)e * 2) = h;
    *reinterpret_cast<__nv_bfloat16*>(g_wprep + (size_t)(2 * m + 1) * 32768 + (size_t)e * 2) = l;
}

// ---------------- tensor-core fused 2-GEMM kernel, 1024 threads ------------
// modes (input transform):
//   0: v=x   1: v=x*BNa   2: v=(BNa.A*x+BNb.A*x2)/deg+(BNa.C+BNb.C)*(deg>0)
//   3: v=BNa(x)+BNb(x2)
// wmode: 0 write out; 1 write out + red aggp[dst] + deg; 2 red aggp only
// NF: node-final semantics — no bias, no ELU, GEMM1->out, GEMM2->out2, no stats
template <bool GATHER, bool NF>
__global__ void __launch_bounds__(1024, 1)
tc_mlp_tpl(const float* __restrict__ X, const float* __restrict__ X2,
           int m1, int m2,
           const float* __restrict__ B1, const float* __restrict__ B2,
           float* __restrict__ out, float* __restrict__ out2,
           int nrows, int mode, int stage,
           int sAi, const float* __restrict__ gA, const float* __restrict__ btA, float cntA,
           int sBi, const float* __restrict__ gB, const float* __restrict__ btB, float cntB,
           const float* __restrict__ degp,
           int wmode, float* __restrict__ aggp,
           const int* __restrict__ srcI, const int* __restrict__ dstI)
{
    extern __shared__ unsigned char smem[];
    unsigned char* Ah  = smem;
    unsigned char* Al  = smem + TILE_BYTES_PAD;
    unsigned char* W1h = smem + 2 * TILE_BYTES_PAD;
    unsigned char* W1l = smem + 3 * TILE_BYTES_PAD;
    unsigned char* W2h = smem + 4 * TILE_BYTES_PAD;
    unsigned char* W2l = smem + 5 * TILE_BYTES_PAD;
    __shared__ float sB1[128], sB2[128], sPA[128], sPC[128], sPA2[128], sPC2[128];
    __shared__ float sInv[128], sF[128];
    __shared__ int sSrc[128], sDst[128];

    const int tid = threadIdx.x, wid = tid >> 5, lane = tid & 31;
    const int wm = wid & 3, wn = wid >> 2;   // warp tile: rows 32*wm, cols 16*wn
    const int g = lane >> 2, tig = lane & 3;
    const int row0 = blockIdx.x * 128;

    // ---- async W1 prefetch (group old), W2 prefetch (group young) ----
    {
        const char* g1 = (const char*)(g_wprep + (size_t)(2 * m1) * 32768);
        const char* g2 = (const char*)(g_wprep + (size_t)(2 * m2) * 32768);
#pragma unroll
        for (int t = 0; t < 2; t++) {
            int idx = tid + 1024 * t;
            uint32_t off = (uint32_t)((idx >> 4) * TILE_PITCH + (idx & 15) * 16);
            CP_ASYNC16(smem_u32(W1h + off), g1 + (size_t)idx * 16);
            CP_ASYNC16(smem_u32(W1l + off), g1 + 32768 + (size_t)idx * 16);
        }
        CP_COMMIT();
#pragma unroll
        for (int t = 0; t < 2; t++) {
            int idx = tid + 1024 * t;
            uint32_t off = (uint32_t)((idx >> 4) * TILE_PITCH + (idx & 15) * 16);
            CP_ASYNC16(smem_u32(W2h + off), g2 + (size_t)idx * 16);
            CP_ASYNC16(smem_u32(W2l + off), g2 + 32768 + (size_t)idx * 16);
        }
        CP_COMMIT();
    }

    if (tid < 128) {
        if (!NF) { sB1[tid] = B1[tid]; sB2[tid] = B2[tid]; }
        if (mode >= 1) {
            float A, C;
            bn_coeff(sAi, cntA, gA, btA, tid, A, C);
            sPA[tid] = A; sPC[tid] = C;
        }
        if (mode >= 2) {
            float A, C;
            bn_coeff(sBi, cntB, gB, btB, tid, A, C);
            sPA2[tid] = A; sPC2[tid] = C;
            if (mode == 2) {
                int r = row0 + tid;
                float dg = (r < nrows) ? degp[r] : 0.f;
                sInv[tid] = 1.f / fmaxf(dg, 1.f);
                sF[tid] = dg > 0.f ? 1.f : 0.f;
            }
        }
        if (GATHER || wmode >= 1) {
            int gr = row0 + tid;
            sDst[tid] = (gr < nrows) ? dstI[gr] : 0;
            if (GATHER) sSrc[tid] = (gr < nrows) ? srcI[gr] : 0;
        }
    }
    __syncthreads();

    // ---- coalesced load + split A tile ----
#pragma unroll
    for (int t = 0; t < 2; t++) {
        int q = tid + 1024 * t;       // 2048 groups of 8 floats
        int r = q >> 4;
        int kp = (q & 15) << 3;
        int gr = row0 + r;
        float v[8];
        if (gr < nrows) {
            float4 a = *reinterpret_cast<const float4*>(X + (size_t)gr * D + kp);
            float4 b = *reinterpret_cast<const float4*>(X + (size_t)gr * D + kp + 4);
            v[0] = a.x; v[1] = a.y; v[2] = a.z; v[3] = a.w;
            v[4] = b.x; v[5] = b.y; v[6] = b.z; v[7] = b.w;
            if (mode == 1) {
#pragma unroll
                for (int i = 0; i < 8; i++) v[i] = v[i] * sPA[kp + i] + sPC[kp + i];
            } else if (mode >= 2) {
                float u[8];
                float4 c = *reinterpret_cast<const float4*>(X2 + (size_t)gr * D + kp);
                float4 d2 = *reinterpret_cast<const float4*>(X2 + (size_t)gr * D + kp + 4);
                u[0] = c.x; u[1] = c.y; u[2] = c.z; u[3] = c.w;
                u[4] = d2.x; u[5] = d2.y; u[6] = d2.z; u[7] = d2.w;
                if (mode == 2) {
                    float inv = sInv[r], f = sF[r];
#pragma unroll
                    for (int i = 0; i < 8; i++)
                        v[i] = (sPA[kp + i] * v[i] + sPA2[kp + i] * u[i]) * inv +
                               (sPC[kp + i] + sPC2[kp + i]) * f;
                } else {
#pragma unroll
                    for (int i = 0; i < 8; i++)
                        v[i] = sPA[kp + i] * v[i] + sPC[kp + i] +
                               sPA2[kp + i] * u[i] + sPC2[kp + i];
                }
            }
        } else {
#pragma unroll
            for (int i = 0; i < 8; i++) v[i] = 0.f;
        }
        split_store8(v, Ah, Al, (uint32_t)(r * TILE_PITCH + kp * 2));
    }
    CP_WAIT1();
    __syncthreads();

    const uint32_t uAh = smem_u32(Ah), uAl = smem_u32(Al);

    // ---- GEMM1 ----
    float acc[2][2][4];
#pragma unroll
    for (int i = 0; i < 2; i++)
#pragma unroll
        for (int j = 0; j < 2; j++) {
            int col = wn * 16 + j * 8 + 2 * tig;
            float b0 = NF ? 0.f : sB1[col];
            float b1v = NF ? 0.f : sB1[col + 1];
            acc[i][j][0] = b0; acc[i][j][1] = b1v;
            acc[i][j][2] = b0; acc[i][j][3] = b1v;
        }
    warp_gemm3(uAh, uAl, smem_u32(W1h), smem_u32(W1l), lane, wm, wn, acc);

    if (NF) {
        // ---- NF epilogue1: write GEMM1 result to out (P1); A unchanged ----
#pragma unroll
        for (int i = 0; i < 2; i++) {
            int r0 = wm * 32 + i * 16 + g;
            int r1 = r0 + 8;
            int gr0 = row0 + r0, gr1 = row0 + r1;
#pragma unroll
            for (int j = 0; j < 2; j++) {
                int col = wn * 16 + j * 8 + 2 * tig;
                if (gr0 < nrows)
                    *reinterpret_cast<float2*>(out + (size_t)gr0 * D + col) =
                        make_float2(acc[i][j][0], acc[i][j][1]);
                if (gr1 < nrows)
                    *reinterpret_cast<float2*>(out + (size_t)gr1 * D + col) =
                        make_float2(acc[i][j][2], acc[i][j][3]);
            }
        }
    } else {
        __syncthreads();  // all warps done reading Ah/Al before rewrite
        // ---- epilogue1: h1 = elu(acc [+ P1[src]+P2[dst]]); re-split ----
#pragma unroll
        for (int i = 0; i < 2; i++) {
            int r0 = wm * 32 + i * 16 + g;
            int r1 = r0 + 8;
#pragma unroll
            for (int j = 0; j < 2; j++) {
                int col = wn * 16 + j * 8 + 2 * tig;
                float v0 = acc[i][j][0], v1 = acc[i][j][1];
                float v2 = acc[i][j][2], v3 = acc[i][j][3];
                if (GATHER) {
                    const float2 p1a = *reinterpret_cast<const float2*>(g_P1 + (size_t)sSrc[r0] * D + col);
                    const float2 p2a = *reinterpret_cast<const float2*>(g_P2 + (size_t)sDst[r0] * D + col);
                    const float2 p1b = *reinterpret_cast<const float2*>(g_P1 + (size_t)sSrc[r1] * D + col);
                    const float2 p2b = *reinterpret_cast<const float2*>(g_P2 + (size_t)sDst[r1] * D + col);
                    v0 += p1a.x + p2a.x; v1 += p1a.y + p2a.y;
                    v2 += p1b.x + p2b.x; v3 += p1b.y + p2b.y;
                }
                v0 = elu1(v0); v1 = elu1(v1); v2 = elu1(v2); v3 = elu1(v3);
                uint32_t hi, lo;
                split2t(v0, v1, hi, lo);
                *reinterpret_cast<uint32_t*>(Ah + r0 * TILE_PITCH + col * 2) = hi;
                *reinterpret_cast<uint32_t*>(Al + r0 * TILE_PITCH + col * 2) = lo;
                split2t(v2, v3, hi, lo);
                *reinterpret_cast<uint32_t*>(Ah + r1 * TILE_PITCH + col * 2) = hi;
                *reinterpret_cast<uint32_t*>(Al + r1 * TILE_PITCH + col * 2) = lo;
            }
        }
    }
    CP_WAIT0();       // W2 resident
    __syncthreads();

    // ---- GEMM2 ----
#pragma unroll
    for (int i = 0; i < 2; i++)
#pragma unroll
        for (int j = 0; j < 2; j++) {
            int col = wn * 16 + j * 8 + 2 * tig;
            float b0 = NF ? 0.f : sB2[col];
            float b1v = NF ? 0.f : sB2[col + 1];
            acc[i][j][0] = b0; acc[i][j][1] = b1v;
            acc[i][j][2] = b0; acc[i][j][3] = b1v;
        }
    warp_gemm3(uAh, uAl, smem_u32(W2h), smem_u32(W2l), lane, wm, wn, acc);

    if (NF) {
        // ---- NF epilogue2: write GEMM2 result to out2 (P2), done ----
#pragma unroll
        for (int i = 0; i < 2; i++) {
            int r0 = wm * 32 + i * 16 + g;
            int r1 = r0 + 8;
            int gr0 = row0 + r0, gr1 = row0 + r1;
#pragma unroll
            for (int j = 0; j < 2; j++) {
                int col = wn * 16 + j * 8 + 2 * tig;
                if (gr0 < nrows)
                    *reinterpret_cast<float2*>(out2 + (size_t)gr0 * D + col) =
                        make_float2(acc[i][j][0], acc[i][j][1]);
                if (gr1 < nrows)
                    *reinterpret_cast<float2*>(out2 + (size_t)gr1 * D + col) =
                        make_float2(acc[i][j][2], acc[i][j][3]);
            }
        }
        return;
    }

    // ---- epilogue2: h2 = elu(acc) -> gmem / red-scatter + smem stats ----
    float* scratch = reinterpret_cast<float*>(W1h);  // 128 x 132 fp32 (safe)
#pragma unroll
    for (int i = 0; i < 2; i++) {
        int r0 = wm * 32 + i * 16 + g;
        int r1 = r0 + 8;
        int gr0 = row0 + r0, gr1 = row0 + r1;
        bool va = gr0 < nrows, vb = gr1 < nrows;
#pragma unroll
        for (int j = 0; j < 2; j++) {
            int col = wn * 16 + j * 8 + 2 * tig;
            float v0 = va ? elu1(acc[i][j][0]) : 0.f;
            float v1 = va ? elu1(acc[i][j][1]) : 0.f;
            float v2 = vb ? elu1(acc[i][j][2]) : 0.f;
            float v3 = vb ? elu1(acc[i][j][3]) : 0.f;
            *reinterpret_cast<float2*>(scratch + r0 * 132 + col) = make_float2(v0, v1);
            *reinterpret_cast<float2*>(scratch + r1 * 132 + col) = make_float2(v2, v3);
            if (wmode <= 1) {
                if (va) *reinterpret_cast<float2*>(out + (size_t)gr0 * D + col) = make_float2(v0, v1);
                if (vb) *reinterpret_cast<float2*>(out + (size_t)gr1 * D + col) = make_float2(v2, v3);
            }
            if (wmode >= 1) {
                if (va) RED2(aggp + (size_t)sDst[r0] * D + col, v0, v1);
                if (vb) RED2(aggp + (size_t)sDst[r1] * D + col, v2, v3);
            }
        }
    }
    if (wmode == 1 && tid < 128 && (row0 + tid) < nrows) {
        asm volatile("red.global.add.f32 [%0], %1;"
                     :: "l"(g_deg + sDst[tid]), "f"(1.f) : "memory");
    }
    __syncthreads();

    {
        int col = tid & 127;
        int rb = (tid >> 7) * 16;
        float s = 0.f, q = 0.f;
#pragma unroll 4
        for (int r = rb; r < rb + 16; r++) {
            float vv = scratch[r * 132 + col];
            s += vv; q += vv * vv;
        }
        atomicAdd(&g_stats[stage * 256 + col], s);
        atomicAdd(&g_stats[stage * 256 + 128 + col], q);
    }
}

// final in-place BN on output (stage-4 coeffs computed per block)
__global__ void norm_out_kernel(float* __restrict__ out, int n4, float cnt,
                                const float* __restrict__ eg,
                                const float* __restrict__ ebt)
{
    __shared__ float sA[128], sC[128];
    if (threadIdx.x < 128) {
        float A, C;
        bn_coeff(4, cnt, eg, ebt, threadIdx.x, A, C);
        sA[threadIdx.x] = A; sC[threadIdx.x] = C;
    }
    __syncthreads();
    int idx = blockIdx.x * blockDim.x + threadIdx.x;
    if (idx >= n4) return;
    int cv = idx & 31;
    float4 A = reinterpret_cast<const float4*>(sA)[cv];
    float4 C = reinterpret_cast<const float4*>(sC)[cv];
    float4 v = reinterpret_cast<float4*>(out)[idx];
    v.x = v.x * A.x + C.x;
    v.y = v.y * A.y + C.y;
    v.z = v.z * A.z + C.z;
    v.w = v.w * A.w + C.w;
    reinterpret_cast<float4*>(out)[idx] = v;
}

// ---------------- host orchestration ----------------
extern "C" void kernel_launch(void* const* d_in, const int* in_sizes, int n_in,
                              void* d_out, int out_size)
{
    if (n_in < 15) return;
    const float* edata = (const float*)d_in[0];
    const int*   src   = (const int*)d_in[1];
    const int*   dst   = (const int*)d_in[2];
    int w = (n_in >= 16) ? 4 : 3;
    const float* W1s = (const float*)d_in[w + 0];
    const float* b1s = (const float*)d_in[w + 1];
    const float* W2s = (const float*)d_in[w + 2];
    const float* b2s = (const float*)d_in[w + 3];
    const float* gs  = (const float*)d_in[w + 4];
    const float* bts = (const float*)d_in[w + 5];
    const float* eW1 = (const float*)d_in[w + 6];
    const float* eb1 = (const float*)d_in[w + 7];
    const float* eW2 = (const float*)d_in[w + 8];
    const float* eb2 = (const float*)d_in[w + 9];
    const float* eg  = (const float*)d_in[w + 10];
    const float* ebt = (const float*)d_in[w + 11];

    int E = in_sizes[0] / D;
    int N = 20000;

    float *p_t1, *p_v, *p_w2, *p_P1, *p_P2, *p_aggT, *p_aggU, *p_deg;
    cudaGetSymbolAddress((void**)&p_t1, g_t1);
    cudaGetSymbolAddress((void**)&p_v, g_v);
    cudaGetSymbolAddress((void**)&p_w2, g_w);
    cudaGetSymbolAddress((void**)&p_P1, g_P1);
    cudaGetSymbolAddress((void**)&p_P2, g_P2);
    cudaGetSymbolAddress((void**)&p_aggT, g_aggT);
    cudaGetSymbolAddress((void**)&p_aggU, g_aggU);
    cudaGetSymbolAddress((void**)&p_deg, g_deg);

    cudaFuncSetAttribute(tc_mlp_tpl<false, false>, cudaFuncAttributeMaxDynamicSharedMemorySize, TC_SMEM);
    cudaFuncSetAttribute(tc_mlp_tpl<false, true>,  cudaFuncAttributeMaxDynamicSharedMemorySize, TC_SMEM);
    cudaFuncSetAttribute(tc_mlp_tpl<true, false>,  cudaFuncAttributeMaxDynamicSharedMemorySize, TC_SMEM);

    cudaMemsetAsync(p_aggT, 0, (size_t)NODE_CAP * D * sizeof(float), 0);
    cudaMemsetAsync(p_aggU, 0, (size_t)NODE_CAP * D * sizeof(float), 0);
    cudaMemsetAsync(p_deg, 0, NODE_CAP * sizeof(float), 0);

    int egrid = (E + 127) / 128;
    int ngrid = (N + 127) / 128;

    // weight prep: 12 matrices (also zeroes g_stats)
    prep_weights<<<(12 * 16384 + 255) / 256, 256>>>(W1s, W2s, eW1, eW2);

    // edge MLP0: write t1 + raw-scatter to aggT + deg   (stage 0)
    tc_mlp_tpl<false, false><<<egrid, 1024, TC_SMEM>>>(
        edata, nullptr, 0, 1, b1s, b2s, p_t1, nullptr, E, 0, 0,
        0, nullptr, nullptr, 0.f, 0, nullptr, nullptr, 0.f, nullptr,
        1, p_aggT, nullptr, dst);
    // edge MLP1 (input = BN0(t1)): no gmem write; raw-scatter u to aggU (stage 1)
    tc_mlp_tpl<false, false><<<egrid, 1024, TC_SMEM>>>(
        p_t1, nullptr, 2, 3, b1s + 128, b2s + 128, nullptr, nullptr, E, 1, 1,
        0, gs, bts, (float)E, 0, nullptr, nullptr, 0.f, nullptr,
        2, p_aggU, nullptr, dst);
    // node MLP2: input = (A0*aggT + A1*aggU)/deg + (C0+C1)   (stage 2)
    tc_mlp_tpl<false, false><<<ngrid, 1024, TC_SMEM>>>(
        p_aggT, p_aggU, 6, 7, b1s + 256, b2s + 256, p_v, nullptr, N, 2, 2,
        0, gs, bts, (float)E, 1, gs + 128, bts + 128, (float)E, p_deg,
        0, nullptr, nullptr, nullptr);
    // node MLP3 (input = BN2(v))   (stage 3)
    tc_mlp_tpl<false, false><<<ngrid, 1024, TC_SMEM>>>(
        p_v, nullptr, 8, 9, b1s + 384, b2s + 384, p_w2, nullptr, N, 1, 3,
        2, gs + 256, bts + 256, (float)N, 0, nullptr, nullptr, 0.f, nullptr,
        0, nullptr, nullptr, nullptr);
    // node final: h_n = BN2(v)+BN3(w); P1 = h@eW1b, P2 = h@eW1c  (NF path)
    tc_mlp_tpl<false, true><<<ngrid, 1024, TC_SMEM>>>(
        p_v, p_w2, 10, 11, nullptr, nullptr, p_P1, p_P2, N, 3, 0,
        2, gs + 256, bts + 256, (float)N, 3, gs + 384, bts + 384, (float)N, nullptr,
        0, nullptr, nullptr, nullptr);
    // final edge MLP (with gathers) -> d_out (pre-BN)   (stage 4)
    tc_mlp_tpl<true, false><<<egrid, 1024, TC_SMEM>>>(
        edata, nullptr, 4, 5, eb1, eb2, (float*)d_out, nullptr, E, 0, 4,
        0, nullptr, nullptr, 0.f, 0, nullptr, nullptr, 0.f, nullptr,
        0, nullptr, src, dst);
    // final in-place BN
    int n4 = E * (D / 4);
    norm_out_kernel<<<(n4 + 255) / 256, 256>>>((float*)d_out, n4, (float)E, eg, ebt);
}